// round 12
// baseline (speedup 1.0000x reference)
#include <cuda_runtime.h>
#include <cuda_bf16.h>
#include <math.h>

// Problem constants: B=1, C=32, H=W=256, WS=16, OWS=24, NH=2, d=16
#define HWP   65536
#define NKEY  576
#define NQ    256
#define NWIN  256

typedef unsigned long long u64;
typedef unsigned int u32;

#define LOG2E 1.4426950408889634f

// attn smem layout (both z resident)
#define KSTRIDE 24
#define VSTRIDE 584
#define KBYTES (NKEY * KSTRIDE * 2)          // 27648
#define VBYTES (16 * VSTRIDE * 2)            // 18688
#define SMEM_ATTN (2 * KBYTES + 2 * VBYTES)  // 92672

#define PPW 8

// front kernel block ranges
#define FB_STEM 256
#define FB_CHW  2048
#define FB_BIAS 288
#define FB_TOTAL (FB_STEM + FB_CHW + FB_BIAS)   // 2592

// ---------------- scratch ----------------
__device__ float          g_xhwc [HWP * 32];
__device__ float          g_t4   [HWP * 32];
__device__ __nv_bfloat16  g_qbf  [2 * HWP * 32];
__device__ __nv_bfloat16  g_kvbf [2 * HWP * 64];
__device__ __nv_bfloat16  g_attbf[2 * HWP * 32];
__device__ u64            g_biasF[2 * NQ * 36 * 4];
__device__ float          g_stats[64];
__device__ float          g_part [512 * 64];

// ---------------- helpers ----------------
__device__ __forceinline__ u64 f2pack(float lo, float hi) {
    u64 r; asm("mov.b64 %0, {%1, %2};" : "=l"(r) : "f"(lo), "f"(hi)); return r;
}
__device__ __forceinline__ float2 f2unpack(u64 v) {
    float2 f; asm("mov.b64 {%0, %1}, %2;" : "=f"(f.x), "=f"(f.y) : "l"(v)); return f;
}
__device__ __forceinline__ u64 f2fma(u64 a, u64 b, u64 c) {
    u64 d; asm("fma.rn.f32x2 %0, %1, %2, %3;" : "=l"(d) : "l"(a), "l"(b), "l"(c)); return d;
}
__device__ __forceinline__ float ex2f(float x) {
    float y; asm("ex2.approx.f32 %0, %1;" : "=f"(y) : "f"(x)); return y;
}
__device__ __forceinline__ u32 bfpack(float lo, float hi) {
    u32 d; asm("cvt.rn.bf16x2.f32 %0, %1, %2;" : "=r"(d) : "f"(hi), "f"(lo)); return d;
}
__device__ __forceinline__ float warp_sum(float v) {
#pragma unroll
    for (int o = 16; o; o >>= 1) v += __shfl_xor_sync(0xffffffffu, v, o);
    return v;
}
__device__ __forceinline__ float gelu_tanh(float x) {
    float z = 0.7978845608028654f * (x + 0.044715f * x * x * x);
    float e = ex2f(2.8853900817779268f * z);
    float t = 1.f - __fdividef(2.f, e + 1.f);
    return 0.5f * x * (1.f + t);
}
__device__ __forceinline__ void mma_bf16(float* d, const u32* a, const u32* b, const float* c) {
    asm("mma.sync.aligned.m16n8k16.row.col.f32.bf16.bf16.f32 "
        "{%0,%1,%2,%3}, {%4,%5,%6,%7}, {%8,%9}, {%10,%11,%12,%13};"
        : "=f"(d[0]), "=f"(d[1]), "=f"(d[2]), "=f"(d[3])
        : "r"(a[0]), "r"(a[1]), "r"(a[2]), "r"(a[3]),
          "r"(b[0]), "r"(b[1]),
          "f"(c[0]), "f"(c[1]), "f"(c[2]), "f"(c[3]));
}

// ---------------- front branch: fused stem ----------------
__device__ void stem_body(int blk,
    const float* __restrict__ depth,
    const float* __restrict__ cw1, const float* __restrict__ cb1,
    const float* __restrict__ cw2, const float* __restrict__ cb2,
    const float* __restrict__ cw3, const float* __restrict__ cb3,
    const float* __restrict__ cw4, const float* __restrict__ cb4,
    float* __restrict__ t4) {
    __shared__ float w1[72], b1s[8], w2[128], b2s[16];
    __shared__ u64 w3p[1152];
    __shared__ u64 w4p[256];
    __shared__ float b3[16], b4[32];
    __shared__ float t2s[324][17];
    int tid = threadIdx.x;
    if (tid < 72)  w1[tid]  = cw1[tid];
    if (tid < 8)   b1s[tid] = cb1[tid];
    if (tid < 128) w2[tid]  = cw2[tid];
    if (tid < 16)  b2s[tid] = cb2[tid];
    for (int i = tid; i < 1152; i += 256) {
        int oc = i / 72, r = i - oc * 72, tap = r >> 3, ic2 = r & 7;
        w3p[i] = f2pack(cw3[oc * 144 + (2 * ic2) * 9 + tap],
                        cw3[oc * 144 + (2 * ic2 + 1) * 9 + tap]);
    }
    if (tid < 256) {
        int c4 = tid >> 3, o2 = tid & 7;
        w4p[tid] = f2pack(cw4[c4 * 16 + 2 * o2], cw4[c4 * 16 + 2 * o2 + 1]);
    }
    if (tid < 16) b3[tid] = cb3[tid];
    if (tid < 32) b4[tid] = cb4[tid];
    __syncthreads();

    int ty0 = (blk >> 4) << 4;
    int tx0 = (blk & 15) << 4;

    for (int h = tid; h < 324; h += 256) {
        int hy = h / 18, hx = h - hy * 18;
        int gy = ty0 + hy - 1, gx = tx0 + hx - 1;
        float out16[16];
        if ((unsigned)gy < 256u && (unsigned)gx < 256u) {
            float d[9];
#pragma unroll
            for (int tap = 0; tap < 9; tap++) {
                int yy = gy + tap / 3 - 1, xx = gx + tap % 3 - 1;
                d[tap] = ((unsigned)yy < 256u && (unsigned)xx < 256u)
                             ? depth[(yy << 8) + xx] : 0.f;
            }
            float c1[8];
#pragma unroll
            for (int o = 0; o < 8; o++) {
                float a = b1s[o];
#pragma unroll
                for (int tap = 0; tap < 9; tap++) a += d[tap] * w1[o * 9 + tap];
                c1[o] = fmaxf(a, 0.f);
            }
#pragma unroll
            for (int o2 = 0; o2 < 16; o2++) {
                float a = b2s[o2];
#pragma unroll
                for (int o = 0; o < 8; o++) a += c1[o] * w2[o2 * 8 + o];
                out16[o2] = fmaxf(a, 0.f);
            }
        } else {
#pragma unroll
            for (int o2 = 0; o2 < 16; o2++) out16[o2] = 0.f;
        }
#pragma unroll
        for (int o2 = 0; o2 < 16; o2++) t2s[h][o2] = out16[o2];
    }
    __syncthreads();

    int py = tid >> 4, px = tid & 15;
    u64 acc2[16];
#pragma unroll
    for (int i = 0; i < 16; i++) acc2[i] = 0ULL;
#pragma unroll 1
    for (int tap = 0; tap < 9; tap++) {
        int hh = (py + tap / 3) * 18 + (px + tap % 3);
        const float* src = &t2s[hh][0];
        u64 in2[8];
#pragma unroll
        for (int k = 0; k < 8; k++) in2[k] = f2pack(src[2 * k], src[2 * k + 1]);
        const u64* wt = &w3p[tap * 8];
#pragma unroll
        for (int oc = 0; oc < 16; oc++) {
            const u64* wr = wt + oc * 72;
#pragma unroll
            for (int k = 0; k < 8; k++) acc2[oc] = f2fma(in2[k], wr[k], acc2[oc]);
        }
    }
    float c3[16];
#pragma unroll
    for (int oc = 0; oc < 16; oc++) {
        float2 f = f2unpack(acc2[oc]);
        c3[oc] = fmaxf(f.x + f.y + b3[oc], 0.f);
    }
    u64 a2[8];
#pragma unroll
    for (int o2 = 0; o2 < 8; o2++) a2[o2] = f2pack(c3[2 * o2], c3[2 * o2 + 1]);
    int p = (ty0 + py) * 256 + tx0 + px;
    float* dst = t4 + (size_t)p * 32;
#pragma unroll
    for (int c4 = 0; c4 < 32; c4++) {
        u64 r = 0ULL;
#pragma unroll
        for (int o2 = 0; o2 < 8; o2++) r = f2fma(a2[o2], w4p[c4 * 8 + o2], r);
        float2 f = f2unpack(r);
        dst[c4] = f.x + f.y + b4[c4];
    }
}

// ---------------- front branch: CHW -> HWC transpose ----------------
__device__ void chw_body(int blk, const float* __restrict__ x, float* __restrict__ xh) {
    __shared__ float sm[32][33];
    int p0 = blk * 32;
    int tx = threadIdx.x & 31, ty = threadIdx.x >> 5;
    for (int c = ty; c < 32; c += 8) sm[c][tx] = x[c * HWP + p0 + tx];
    __syncthreads();
    for (int r = ty; r < 32; r += 8) xh[(p0 + r) * 32 + tx] = sm[tx][r];
}

// ---------------- front branch: bias fragments ----------------
__device__ void bias_body(int blk, const int* __restrict__ rpi, const float* __restrict__ rpb,
                          u64* __restrict__ biasF) {
    int idx = blk * 256 + threadIdx.x;
    int tig = idx & 3;
    int t2 = idx >> 2;
    int ch = t2 % 36;
    int t3 = t2 / 36;
    int q = t3 & 255;
    int h = t3 >> 8;
    int k0 = ch * 16 + 2 * tig;
    u64 r = 0;
#pragma unroll
    for (int e = 0; e < 4; e++) {
        int k = k0 + (e >> 1) * 8 + (e & 1);
        float v = rpb[rpi[q * NKEY + k] * 2 + h] * LOG2E;
        unsigned short us = __bfloat16_as_ushort(__float2bfloat16(v));
        r |= (u64)us << (16 * e);
    }
    biasF[idx] = r;
}

// ---------------- K1: packed front kernel (stem | chw2hwc | biasF) ----------------
__global__ __launch_bounds__(256) void front_kernel(
    const float* __restrict__ x, const float* __restrict__ depth,
    const int* __restrict__ rpi, const float* __restrict__ rpb,
    const float* __restrict__ cw1, const float* __restrict__ cb1,
    const float* __restrict__ cw2, const float* __restrict__ cb2,
    const float* __restrict__ cw3, const float* __restrict__ cb3,
    const float* __restrict__ cw4, const float* __restrict__ cb4,
    float* __restrict__ t4, float* __restrict__ xh, u64* __restrict__ biasF) {
    int b = blockIdx.x;
    if (b < FB_STEM) {
        stem_body(b, depth, cw1, cb1, cw2, cb2, cw3, cb3, cw4, cb4, t4);
    } else if (b < FB_STEM + FB_CHW) {
        chw_body(b - FB_STEM, x, xh);
    } else {
        bias_body(b - FB_STEM - FB_CHW, rpi, rpb, biasF);
    }
}

// ---------------- K3a: instance-norm partial sums ----------------
__global__ __launch_bounds__(256) void inorm_part_kernel(const float* __restrict__ t4,
                                                         float* __restrict__ part) {
    int tid = threadIdx.x;
    size_t base = (size_t)blockIdx.x * 4096;
    float s[4] = {0, 0, 0, 0}, s2[4] = {0, 0, 0, 0};
    const float4* src = (const float4*)(t4 + base);
#pragma unroll
    for (int it = 0; it < 4; it++) {
        float4 v = src[it * 256 + tid];
        s[0] += v.x; s2[0] += v.x * v.x;
        s[1] += v.y; s2[1] += v.y * v.y;
        s[2] += v.z; s2[2] += v.z * v.z;
        s[3] += v.w; s2[3] += v.w * v.w;
    }
    __shared__ float sa[256][4], sb[256][4];
#pragma unroll
    for (int k = 0; k < 4; k++) { sa[tid][k] = s[k]; sb[tid][k] = s2[k]; }
    __syncthreads();
    if (tid < 32) {
        int grp = tid >> 2, k = tid & 3;
        float a = 0.f, b = 0.f;
#pragma unroll
        for (int t8 = 0; t8 < 32; t8++) {
            a += sa[t8 * 8 + grp][k];
            b += sb[t8 * 8 + grp][k];
        }
        part[blockIdx.x * 64 + tid] = a;
        part[blockIdx.x * 64 + 32 + tid] = b;
    }
}

// ---------------- K3b: instance-norm final reduce ----------------
__global__ __launch_bounds__(1024) void inorm_final_kernel(const float* __restrict__ part,
                                                           float* __restrict__ stats) {
    int tid = threadIdx.x;
    int c = tid & 31, g = tid >> 5;
    double a = 0.0, b = 0.0;
#pragma unroll
    for (int i = 0; i < 16; i++) {
        int blk = g * 16 + i;
        a += (double)part[blk * 64 + c];
        b += (double)part[blk * 64 + 32 + c];
    }
    __shared__ double sa[32][33], sb[32][33];
    sa[g][c] = a; sb[g][c] = b;
    __syncthreads();
    for (int o = 16; o; o >>= 1) {
        if (g < o) {
            sa[g][c] += sa[g + o][c];
            sb[g][c] += sb[g + o][c];
        }
        __syncthreads();
    }
    if (tid < 32) {
        double mean = sa[0][tid] / (double)HWP;
        double var = sb[0][tid] / (double)HWP - mean * mean;
        stats[tid] = (float)mean;
        stats[32 + tid] = rsqrtf((float)var + 1e-5f);
    }
}

// ---------------- K6: LN(x), LN(f) once; project into both OCABs' q/kv ----------------
__global__ __launch_bounds__(256) void ln_qkv_kernel(
    const float* __restrict__ xhwc, const float* __restrict__ t4,
    const float* __restrict__ stats,
    const float* __restrict__ in_g, const float* __restrict__ in_b,
    const float* __restrict__ n1g, const float* __restrict__ n1b,
    const float* __restrict__ wq, const float* __restrict__ bq,
    const float* __restrict__ wkv, const float* __restrict__ bkv,
    __nv_bfloat16* __restrict__ qbase, __nv_bfloat16* __restrict__ kvbase) {
    __shared__ u64 s_wq2[512], s_wk2[512], s_wv2[512];
    __shared__ float s_bq[32], s_bkv[64], s_g[32], s_b[32], s_A[32], s_C[32];
    __shared__ __align__(16) float s_act[8][32];
    int tid = threadIdx.x;
    for (int idx = tid; idx < 512; idx += 256) {
        int i2 = idx >> 5, l = idx & 31;
        s_wq2[idx] = f2pack(wq[(2 * i2) * 32 + l], wq[(2 * i2 + 1) * 32 + l]);
        s_wk2[idx] = f2pack(wkv[(2 * i2) * 64 + l], wkv[(2 * i2 + 1) * 64 + l]);
        s_wv2[idx] = f2pack(wkv[(2 * i2) * 64 + 32 + l], wkv[(2 * i2 + 1) * 64 + 32 + l]);
    }
    if (tid < 32) {
        s_bq[tid] = bq[tid]; s_g[tid] = n1g[tid]; s_b[tid] = n1b[tid];
        float A = stats[32 + tid] * in_g[tid];
        s_A[tid] = A;
        s_C[tid] = in_b[tid] - stats[tid] * A;
    }
    if (tid < 64) s_bkv[tid] = bkv[tid];
    __syncthreads();
    __nv_bfloat16* q0  = qbase;
    __nv_bfloat16* q1  = qbase + (size_t)HWP * 32;
    __nv_bfloat16* kv0 = kvbase;
    __nv_bfloat16* kv1 = kvbase + (size_t)HWP * 64;
    int lane = tid & 31, w = tid >> 5;
    int pbase = blockIdx.x * (8 * PPW) + w * PPW;
    const float QS = 0.25f * LOG2E;

#pragma unroll 1
    for (int it = 0; it < PPW; it++) {
        int p = pbase + it;
        float xv = xhwc[p * 32 + lane];
        float fvv = t4[p * 32 + lane] * s_A[lane] + s_C[lane];
        float mx = warp_sum(xv) * (1.f / 32.f);
        float dx = xv - mx;
        float vx = warp_sum(dx * dx) * (1.f / 32.f);
        float xn_x = dx * rsqrtf(vx + 1e-5f) * s_g[lane] + s_b[lane];
        float mf = warp_sum(fvv) * (1.f / 32.f);
        float df = fvv - mf;
        float vf = warp_sum(df * df) * (1.f / 32.f);
        float xn_f = df * rsqrtf(vf + 1e-5f) * s_g[lane] + s_b[lane];

        s_act[w][lane] = xn_x;
        __syncwarp();
        {
            u64 aq = 0ULL, ak = 0ULL, av = 0ULL;
#pragma unroll
            for (int i2 = 0; i2 < 16; i2++) {
                u64 x2 = *(const u64*)&s_act[w][2 * i2];
                aq = f2fma(x2, s_wq2[i2 * 32 + lane], aq);
                ak = f2fma(x2, s_wk2[i2 * 32 + lane], ak);
                av = f2fma(x2, s_wv2[i2 * 32 + lane], av);
            }
            float2 fq = f2unpack(aq), fk = f2unpack(ak), fv2 = f2unpack(av);
            q0[p * 32 + lane] = __float2bfloat16((fq.x + fq.y + s_bq[lane]) * QS);
            kv1[p * 64 + lane]      = __float2bfloat16(fk.x + fk.y + s_bkv[lane]);
            kv1[p * 64 + 32 + lane] = __float2bfloat16(fv2.x + fv2.y + s_bkv[lane + 32]);
        }
        __syncwarp();
        s_act[w][lane] = xn_f;
        __syncwarp();
        {
            u64 aq = 0ULL, ak = 0ULL, av = 0ULL;
#pragma unroll
            for (int i2 = 0; i2 < 16; i2++) {
                u64 x2 = *(const u64*)&s_act[w][2 * i2];
                aq = f2fma(x2, s_wq2[i2 * 32 + lane], aq);
                ak = f2fma(x2, s_wk2[i2 * 32 + lane], ak);
                av = f2fma(x2, s_wv2[i2 * 32 + lane], av);
            }
            float2 fq = f2unpack(aq), fk = f2unpack(ak), fv2 = f2unpack(av);
            q1[p * 32 + lane] = __float2bfloat16((fq.x + fq.y + s_bq[lane]) * QS);
            kv0[p * 64 + lane]      = __float2bfloat16(fk.x + fk.y + s_bkv[lane]);
            kv0[p * 64 + 32 + lane] = __float2bfloat16(fv2.x + fv2.y + s_bkv[lane + 32]);
        }
        __syncwarp();
    }
}

// ---------------- K7: flash attention, both z per block (bias loads shared) ----------------
__global__ __launch_bounds__(256) void attn_kernel(
    const __nv_bfloat16* __restrict__ qbase, const __nv_bfloat16* __restrict__ kvbase,
    const u64* __restrict__ biasF, __nv_bfloat16* __restrict__ outbase) {
    extern __shared__ __align__(16) char smraw[];
    int win = blockIdx.x, head = blockIdx.y;
    int wy = win >> 4, wx = win & 15;
    int t = threadIdx.x;
    int warp = t >> 5, lane = t & 31;
    int gid = lane >> 2, tig = lane & 3;

    __nv_bfloat16* ksmz[2] = {(__nv_bfloat16*)smraw, (__nv_bfloat16*)(smraw + KBYTES)};
    __nv_bfloat16* vsmz[2] = {(__nv_bfloat16*)(smraw + 2 * KBYTES),
                              (__nv_bfloat16*)(smraw + 2 * KBYTES + VBYTES)};

    for (int j = t; j < NKEY; j += 256) {
        int jy = j / 24, jx = j - jy * 24;
        int yy = (wy << 4) - 4 + jy, xx = (wx << 4) - 4 + jx;
        bool inb = ((unsigned)yy < 256u && (unsigned)xx < 256u);
#pragma unroll
        for (int z = 0; z < 2; z++) {
            uint4 k0 = make_uint4(0, 0, 0, 0), k1 = k0, v0 = k0, v1 = k0;
            if (inb) {
                const __nv_bfloat16* base = kvbase + (size_t)z * HWP * 64 +
                                            ((size_t)((yy << 8) + xx) << 6) + (head << 4);
                k0 = *(const uint4*)base;
                k1 = *(const uint4*)(base + 8);
                v0 = *(const uint4*)(base + 32);
                v1 = *(const uint4*)(base + 40);
            }
            *(uint4*)(ksmz[z] + j * KSTRIDE)     = k0;
            *(uint4*)(ksmz[z] + j * KSTRIDE + 8) = k1;
            u32 vw[8] = {v0.x, v0.y, v0.z, v0.w, v1.x, v1.y, v1.z, v1.w};
#pragma unroll
            for (int i = 0; i < 8; i++) {
                __nv_bfloat162 pr = *(const __nv_bfloat162*)&vw[i];
                vsmz[z][(2 * i) * VSTRIDE + j]     = pr.x;
                vsmz[z][(2 * i + 1) * VSTRIDE + j] = pr.y;
            }
        }
    }

    u32 qa[2][2][4];
    int qwb = warp * 32;
#pragma unroll
    for (int z = 0; z < 2; z++) {
        const __nv_bfloat16* q = qbase + (size_t)z * HWP * 32;
#pragma unroll
        for (int m = 0; m < 2; m++) {
            int r0 = qwb + m * 16 + gid;
            int r1 = r0 + 8;
            int px0 = ((wy << 4) + (r0 >> 4)) * 256 + (wx << 4) + (r0 & 15);
            int px1 = ((wy << 4) + (r1 >> 4)) * 256 + (wx << 4) + (r1 & 15);
            const __nv_bfloat16* q0p = q + (size_t)px0 * 32 + (head << 4);
            const __nv_bfloat16* q1p = q + (size_t)px1 * 32 + (head << 4);
            qa[z][m][0] = *(const u32*)(q0p + 2 * tig);
            qa[z][m][1] = *(const u32*)(q1p + 2 * tig);
            qa[z][m][2] = *(const u32*)(q0p + 8 + 2 * tig);
            qa[z][m][3] = *(const u32*)(q1p + 8 + 2 * tig);
        }
    }
    __syncthreads();

    float o[2][2][2][4];
#pragma unroll
    for (int z = 0; z < 2; z++)
#pragma unroll
        for (int m = 0; m < 2; m++)
#pragma unroll
            for (int d = 0; d < 2; d++)
#pragma unroll
                for (int i = 0; i < 4; i++) o[z][m][d][i] = 0.f;
    float l4[2][4] = {{0.f, 0.f, 0.f, 0.f}, {0.f, 0.f, 0.f, 0.f}};

    const u64* bF = biasF + ((size_t)head << 8) * 144;

#pragma unroll 1
    for (int ch = 0; ch < 36; ch++) {
        int kb = ch * 16;
        u64 bw[4];
#pragma unroll
        for (int r4 = 0; r4 < 4; r4++) {
            int qrow = qwb + ((r4 >> 1) << 4) + ((r4 & 1) << 3) + gid;
            bw[r4] = bF[(qrow * 36 + ch) * 4 + tig];
        }
#pragma unroll
        for (int z = 0; z < 2; z++) {
            u32 kf[2][2];
#pragma unroll
            for (int nt = 0; nt < 2; nt++) {
                const __nv_bfloat16* kr = ksmz[z] + (kb + nt * 8 + gid) * KSTRIDE + 2 * tig;
                kf[nt][0] = *(const u32*)kr;
                kf[nt][1] = *(const u32*)(kr + 8);
            }
            u32 vb[2][2];
#pragma unroll
            for (int dt = 0; dt < 2; dt++) {
                const __nv_bfloat16* vr = vsmz[z] + (dt * 8 + gid) * VSTRIDE + kb + 2 * tig;
                vb[dt][0] = *(const u32*)vr;
                vb[dt][1] = *(const u32*)(vr + 8);
            }
#pragma unroll
            for (int m = 0; m < 2; m++) {
                float c0[4] = {0.f, 0.f, 0.f, 0.f}, c1[4] = {0.f, 0.f, 0.f, 0.f};
                mma_bf16(c0, qa[z][m], kf[0], c0);
                mma_bf16(c1, qa[z][m], kf[1], c1);
                u32 bAlo = (u32)bw[m * 2],     bAhi = (u32)(bw[m * 2] >> 32);
                u32 bBlo = (u32)bw[m * 2 + 1], bBhi = (u32)(bw[m * 2 + 1] >> 32);
                float p00 = ex2f(fminf(c0[0] + __int_as_float(bAlo << 16), 80.f));
                float p01 = ex2f(fminf(c0[1] + __int_as_float((int)(bAlo & 0xffff0000u)), 80.f));
                float p02 = ex2f(fminf(c0[2] + __int_as_float(bBlo << 16), 80.f));
                float p03 = ex2f(fminf(c0[3] + __int_as_float((int)(bBlo & 0xffff0000u)), 80.f));
                float p10 = ex2f(fminf(c1[0] + __int_as_float(bAhi << 16), 80.f));
                float p11 = ex2f(fminf(c1[1] + __int_as_float((int)(bAhi & 0xffff0000u)), 80.f));
                float p12 = ex2f(fminf(c1[2] + __int_as_float(bBhi << 16), 80.f));
                float p13 = ex2f(fminf(c1[3] + __int_as_float((int)(bBhi & 0xffff0000u)), 80.f));
                l4[z][m * 2]     += (p00 + p01) + (p10 + p11);
                l4[z][m * 2 + 1] += (p02 + p03) + (p12 + p13);
                u32 pa[4];
                pa[0] = bfpack(p00, p01);
                pa[1] = bfpack(p02, p03);
                pa[2] = bfpack(p10, p11);
                pa[3] = bfpack(p12, p13);
                mma_bf16(o[z][m][0], pa, vb[0], o[z][m][0]);
                mma_bf16(o[z][m][1], pa, vb[1], o[z][m][1]);
            }
        }
    }

#pragma unroll
    for (int z = 0; z < 2; z++)
#pragma unroll
        for (int r4 = 0; r4 < 4; r4++) {
            l4[z][r4] += __shfl_xor_sync(0xffffffffu, l4[z][r4], 1);
            l4[z][r4] += __shfl_xor_sync(0xffffffffu, l4[z][r4], 2);
            l4[z][r4] = 1.f / l4[z][r4];
        }

#pragma unroll
    for (int z = 0; z < 2; z++) {
        __nv_bfloat16* out = outbase + (size_t)z * HWP * 32;
#pragma unroll
        for (int m = 0; m < 2; m++) {
            int r0 = qwb + m * 16 + gid;
            int r1 = r0 + 8;
            int px0 = ((wy << 4) + (r0 >> 4)) * 256 + (wx << 4) + (r0 & 15);
            int px1 = ((wy << 4) + (r1 >> 4)) * 256 + (wx << 4) + (r1 & 15);
            __nv_bfloat16* o0p = out + (size_t)px0 * 32 + (head << 4);
            __nv_bfloat16* o1p = out + (size_t)px1 * 32 + (head << 4);
            float i0 = l4[z][m * 2], i1 = l4[z][m * 2 + 1];
#pragma unroll
            for (int dt = 0; dt < 2; dt++) {
                *(u32*)(o0p + dt * 8 + 2 * tig) =
                    bfpack(o[z][m][dt][0] * i0, o[z][m][dt][1] * i0);
                *(u32*)(o1p + dt * 8 + 2 * tig) =
                    bfpack(o[z][m][dt][2] * i1, o[z][m][dt][3] * i1);
            }
        }
    }
}

// ---------------- K8: both OCAB tails + final sum + HWC->CHW, fused ----------------
__global__ __launch_bounds__(256) void proj_mlp_kernel(
    const __nv_bfloat16* __restrict__ attbase,
    const float* __restrict__ xhwc, const float* __restrict__ t4,
    const float* __restrict__ x_chw,
    const float* __restrict__ stats,
    const float* __restrict__ in_g, const float* __restrict__ in_b,
    const float* __restrict__ wp, const float* __restrict__ bp,
    const float* __restrict__ n2g, const float* __restrict__ n2b,
    const float* __restrict__ mw1, const float* __restrict__ mb1,
    const float* __restrict__ mw2, const float* __restrict__ mb2,
    float* __restrict__ out) {
    __shared__ u64 s_wp2[512], s_m1a[512], s_m1b[512], s_m2[1024];
    __shared__ float s_bp[32], s_mb1[64], s_mb2[32], s_g[32], s_b[32], s_A[32], s_C[32];
    __shared__ __align__(16) float s_act[8][32];
    __shared__ __align__(16) float s_h[8][64];
    __shared__ float s_o[64][33];
    int tid = threadIdx.x;
    for (int idx = tid; idx < 512; idx += 256) {
        int i2 = idx >> 5, l = idx & 31;
        s_wp2[idx] = f2pack(wp[(2 * i2) * 32 + l], wp[(2 * i2 + 1) * 32 + l]);
        s_m1a[idx] = f2pack(mw1[(2 * i2) * 64 + l], mw1[(2 * i2 + 1) * 64 + l]);
        s_m1b[idx] = f2pack(mw1[(2 * i2) * 64 + 32 + l], mw1[(2 * i2 + 1) * 64 + 32 + l]);
    }
    for (int idx = tid; idx < 1024; idx += 256) {
        int i2 = idx >> 5, l = idx & 31;
        s_m2[idx] = f2pack(mw2[(2 * i2) * 32 + l], mw2[(2 * i2 + 1) * 32 + l]);
    }
    if (tid < 32) {
        s_bp[tid] = bp[tid]; s_mb2[tid] = mb2[tid]; s_g[tid] = n2g[tid]; s_b[tid] = n2b[tid];
        float A = stats[32 + tid] * in_g[tid];
        s_A[tid] = A;
        s_C[tid] = in_b[tid] - stats[tid] * A;
    }
    if (tid < 64) s_mb1[tid] = mb1[tid];
    __syncthreads();
    int lane = tid & 31, w = tid >> 5;
    int p0blk = blockIdx.x * 64;
    int pbase = p0blk + w * PPW;

#pragma unroll 1
    for (int it = 0; it < PPW; it++) {
        int p = pbase + it;
        float xv = xhwc[p * 32 + lane];
        float fvv = t4[p * 32 + lane] * s_A[lane] + s_C[lane];
        float osum = 0.f;
#pragma unroll 1
        for (int z = 0; z < 2; z++) {
            float scv = z ? fvv : xv;
            float a = __bfloat162float(attbase[(size_t)z * HWP * 32 + p * 32 + lane]);
            s_act[w][lane] = a;
            __syncwarp();
            u64 acc = 0ULL;
#pragma unroll
            for (int i2 = 0; i2 < 16; i2++) {
                u64 x2 = *(const u64*)&s_act[w][2 * i2];
                acc = f2fma(x2, s_wp2[i2 * 32 + lane], acc);
            }
            float2 fy = f2unpack(acc);
            float y = fy.x + fy.y + s_bp[lane] + scv;

            float mean = warp_sum(y) * (1.f / 32.f);
            float dv = y - mean;
            float var = warp_sum(dv * dv) * (1.f / 32.f);
            float yn = dv * rsqrtf(var + 1e-5f) * s_g[lane] + s_b[lane];

            __syncwarp();
            s_act[w][lane] = yn;
            __syncwarp();
            u64 h0a = 0ULL, h1a = 0ULL;
#pragma unroll
            for (int i2 = 0; i2 < 16; i2++) {
                u64 x2 = *(const u64*)&s_act[w][2 * i2];
                h0a = f2fma(x2, s_m1a[i2 * 32 + lane], h0a);
                h1a = f2fma(x2, s_m1b[i2 * 32 + lane], h1a);
            }
            float2 f0 = f2unpack(h0a), f1 = f2unpack(h1a);
            float h0 = gelu_tanh(f0.x + f0.y + s_mb1[lane]);
            float h1 = gelu_tanh(f1.x + f1.y + s_mb1[lane + 32]);
            s_h[w][lane] = h0;
            s_h[w][32 + lane] = h1;
            __syncwarp();
            u64 r2 = 0ULL;
#pragma unroll
            for (int i2 = 0; i2 < 32; i2++) {
                u64 g2 = *(const u64*)&s_h[w][2 * i2];
                r2 = f2fma(g2, s_m2[i2 * 32 + lane], r2);
            }
            float2 fr = f2unpack(r2);
            osum += y + fr.x + fr.y + s_mb2[lane];
            __syncwarp();
        }
        s_o[w * PPW + it][lane] = osum;
    }
    __syncthreads();
#pragma unroll
    for (int e = tid; e < 2048; e += 256) {
        int c = e >> 6, px = e & 63;
        int gp = p0blk + px;
        out[c * HWP + gp] = s_o[px][c] + x_chw[c * HWP + gp];
    }
}

// ---------------- launch ----------------
extern "C" void kernel_launch(void* const* d_in, const int* in_sizes, int n_in,
                              void* d_out, int out_size) {
    const float* x    = (const float*)d_in[0];
    const float* dep  = (const float*)d_in[1];
    const int*   rpi  = (const int*)  d_in[2];
    const float* cw1  = (const float*)d_in[3];
    const float* cb1  = (const float*)d_in[4];
    const float* cw2  = (const float*)d_in[5];
    const float* cb2  = (const float*)d_in[6];
    const float* cw3  = (const float*)d_in[7];
    const float* cb3  = (const float*)d_in[8];
    const float* cw4  = (const float*)d_in[9];
    const float* cb4  = (const float*)d_in[10];
    const float* in_g = (const float*)d_in[11];
    const float* in_b = (const float*)d_in[12];
    const float* n1g  = (const float*)d_in[13];
    const float* n1b  = (const float*)d_in[14];
    const float* wq   = (const float*)d_in[15];
    const float* bq   = (const float*)d_in[16];
    const float* wkv  = (const float*)d_in[17];
    const float* bkv  = (const float*)d_in[18];
    const float* rpb  = (const float*)d_in[19];
    const float* wp   = (const float*)d_in[20];
    const float* bp   = (const float*)d_in[21];
    const float* n2g  = (const float*)d_in[22];
    const float* n2b  = (const float*)d_in[23];
    const float* mw1  = (const float*)d_in[24];
    const float* mb1  = (const float*)d_in[25];
    const float* mw2  = (const float*)d_in[26];
    const float* mb2  = (const float*)d_in[27];
    float* out = (float*)d_out;

    void *p_xhwc, *p_t4, *p_q, *p_kv, *p_att, *p_bias, *p_stats, *p_part;
    cudaGetSymbolAddress(&p_xhwc, g_xhwc);
    cudaGetSymbolAddress(&p_t4, g_t4);
    cudaGetSymbolAddress(&p_q, g_qbf);
    cudaGetSymbolAddress(&p_kv, g_kvbf);
    cudaGetSymbolAddress(&p_att, g_attbf);
    cudaGetSymbolAddress(&p_bias, g_biasF);
    cudaGetSymbolAddress(&p_stats, g_stats);
    cudaGetSymbolAddress(&p_part, g_part);

    cudaFuncSetAttribute(attn_kernel, cudaFuncAttributeMaxDynamicSharedMemorySize, SMEM_ATTN);

    front_kernel<<<FB_TOTAL, 256>>>(x, dep, rpi, rpb, cw1, cb1, cw2, cb2,
                                    cw3, cb3, cw4, cb4,
                                    (float*)p_t4, (float*)p_xhwc, (u64*)p_bias);
    inorm_part_kernel<<<512, 256>>>((float*)p_t4, (float*)p_part);
    inorm_final_kernel<<<1, 1024>>>((float*)p_part, (float*)p_stats);

    ln_qkv_kernel<<<HWP / (8 * PPW), 256>>>(
        (float*)p_xhwc, (float*)p_t4, (float*)p_stats, in_g, in_b, n1g, n1b,
        wq, bq, wkv, bkv, (__nv_bfloat16*)p_q, (__nv_bfloat16*)p_kv);
    attn_kernel<<<dim3(NWIN, 2), 256, SMEM_ATTN>>>((__nv_bfloat16*)p_q,
                                                   (__nv_bfloat16*)p_kv,
                                                   (u64*)p_bias,
                                                   (__nv_bfloat16*)p_att);
    proj_mlp_kernel<<<HWP / 64, 256>>>(
        (__nv_bfloat16*)p_att, (float*)p_xhwc, (float*)p_t4, x, (float*)p_stats,
        in_g, in_b, wp, bp, n2g, n2b, mw1, mb1, mw2, mb2, out);
}

// round 13
// speedup vs baseline: 1.1059x; 1.1059x over previous
#include <cuda_runtime.h>
#include <cuda_bf16.h>
#include <math.h>

// Problem constants: B=1, C=32, H=W=256, WS=16, OWS=24, NH=2, d=16
#define HWP   65536
#define NKEY  576
#define NQ    256
#define NWIN  256

typedef unsigned long long u64;
typedef unsigned int u32;

#define LOG2E 1.4426950408889634f

// attn smem layout (both z resident)
#define KSTRIDE 24
#define VSTRIDE 584
#define KBYTES (NKEY * KSTRIDE * 2)          // 27648
#define VBYTES (16 * VSTRIDE * 2)            // 18688
#define SMEM_ATTN (2 * KBYTES + 2 * VBYTES)  // 92672

#define PPW 8

// ---------------- scratch ----------------
__device__ float          g_xhwc [HWP * 32];
__device__ float          g_t4   [HWP * 32];
__device__ __nv_bfloat16  g_qbf  [2 * HWP * 32];
__device__ __nv_bfloat16  g_kvbf [2 * HWP * 64];
__device__ __nv_bfloat16  g_attbf[2 * HWP * 32];
__device__ u64            g_biasF[2 * NQ * 36 * 4];
__device__ float          g_stats[64];
__device__ float          g_part [512 * 64];

// ---------------- helpers ----------------
__device__ __forceinline__ u64 f2pack(float lo, float hi) {
    u64 r; asm("mov.b64 %0, {%1, %2};" : "=l"(r) : "f"(lo), "f"(hi)); return r;
}
__device__ __forceinline__ float2 f2unpack(u64 v) {
    float2 f; asm("mov.b64 {%0, %1}, %2;" : "=f"(f.x), "=f"(f.y) : "l"(v)); return f;
}
__device__ __forceinline__ u64 f2fma(u64 a, u64 b, u64 c) {
    u64 d; asm("fma.rn.f32x2 %0, %1, %2, %3;" : "=l"(d) : "l"(a), "l"(b), "l"(c)); return d;
}
__device__ __forceinline__ float ex2f(float x) {
    float y; asm("ex2.approx.f32 %0, %1;" : "=f"(y) : "f"(x)); return y;
}
__device__ __forceinline__ u32 bfpack(float lo, float hi) {
    u32 d; asm("cvt.rn.bf16x2.f32 %0, %1, %2;" : "=r"(d) : "f"(hi), "f"(lo)); return d;
}
__device__ __forceinline__ float warp_sum(float v) {
#pragma unroll
    for (int o = 16; o; o >>= 1) v += __shfl_xor_sync(0xffffffffu, v, o);
    return v;
}
__device__ __forceinline__ float gelu_tanh(float x) {
    float z = 0.7978845608028654f * (x + 0.044715f * x * x * x);
    float e = ex2f(2.8853900817779268f * z);
    float t = 1.f - __fdividef(2.f, e + 1.f);
    return 0.5f * x * (1.f + t);
}
__device__ __forceinline__ void mma_bf16(float* d, const u32* a, const u32* b, const float* c) {
    asm("mma.sync.aligned.m16n8k16.row.col.f32.bf16.bf16.f32 "
        "{%0,%1,%2,%3}, {%4,%5,%6,%7}, {%8,%9}, {%10,%11,%12,%13};"
        : "=f"(d[0]), "=f"(d[1]), "=f"(d[2]), "=f"(d[3])
        : "r"(a[0]), "r"(a[1]), "r"(a[2]), "r"(a[3]),
          "r"(b[0]), "r"(b[1]),
          "f"(c[0]), "f"(c[1]), "f"(c[2]), "f"(c[3]));
}

// ---------------- K0: CHW -> HWC transpose of x ----------------
__global__ void chw2hwc_kernel(const float* __restrict__ x, float* __restrict__ xh) {
    __shared__ float sm[32][33];
    int p0 = blockIdx.x * 32;
    int tx = threadIdx.x, ty = threadIdx.y;
    for (int c = ty; c < 32; c += 8) sm[c][tx] = x[c * HWP + p0 + tx];
    __syncthreads();
    for (int r = ty; r < 32; r += 8) xh[(p0 + r) * 32 + tx] = sm[tx][r];
}

// ---------------- K1: fused stem ----------------
__global__ __launch_bounds__(256) void stem_fused_kernel(
    const float* __restrict__ depth,
    const float* __restrict__ cw1, const float* __restrict__ cb1,
    const float* __restrict__ cw2, const float* __restrict__ cb2,
    const float* __restrict__ cw3, const float* __restrict__ cb3,
    const float* __restrict__ cw4, const float* __restrict__ cb4,
    float* __restrict__ t4) {
    __shared__ float w1[72], b1s[8], w2[128], b2s[16];
    __shared__ u64 w3p[1152];
    __shared__ u64 w4p[256];
    __shared__ float b3[16], b4[32];
    __shared__ float t2s[324][17];
    int tid = threadIdx.x;
    if (tid < 72)  w1[tid]  = cw1[tid];
    if (tid < 8)   b1s[tid] = cb1[tid];
    if (tid < 128) w2[tid]  = cw2[tid];
    if (tid < 16)  b2s[tid] = cb2[tid];
    for (int i = tid; i < 1152; i += 256) {
        int oc = i / 72, r = i - oc * 72, tap = r >> 3, ic2 = r & 7;
        w3p[i] = f2pack(cw3[oc * 144 + (2 * ic2) * 9 + tap],
                        cw3[oc * 144 + (2 * ic2 + 1) * 9 + tap]);
    }
    if (tid < 256) {
        int c4 = tid >> 3, o2 = tid & 7;
        w4p[tid] = f2pack(cw4[c4 * 16 + 2 * o2], cw4[c4 * 16 + 2 * o2 + 1]);
    }
    if (tid < 16) b3[tid] = cb3[tid];
    if (tid < 32) b4[tid] = cb4[tid];
    __syncthreads();

    int ty0 = (blockIdx.x >> 4) << 4;
    int tx0 = (blockIdx.x & 15) << 4;

    for (int h = tid; h < 324; h += 256) {
        int hy = h / 18, hx = h - hy * 18;
        int gy = ty0 + hy - 1, gx = tx0 + hx - 1;
        float out16[16];
        if ((unsigned)gy < 256u && (unsigned)gx < 256u) {
            float d[9];
#pragma unroll
            for (int tap = 0; tap < 9; tap++) {
                int yy = gy + tap / 3 - 1, xx = gx + tap % 3 - 1;
                d[tap] = ((unsigned)yy < 256u && (unsigned)xx < 256u)
                             ? depth[(yy << 8) + xx] : 0.f;
            }
            float c1[8];
#pragma unroll
            for (int o = 0; o < 8; o++) {
                float a = b1s[o];
#pragma unroll
                for (int tap = 0; tap < 9; tap++) a += d[tap] * w1[o * 9 + tap];
                c1[o] = fmaxf(a, 0.f);
            }
#pragma unroll
            for (int o2 = 0; o2 < 16; o2++) {
                float a = b2s[o2];
#pragma unroll
                for (int o = 0; o < 8; o++) a += c1[o] * w2[o2 * 8 + o];
                out16[o2] = fmaxf(a, 0.f);
            }
        } else {
#pragma unroll
            for (int o2 = 0; o2 < 16; o2++) out16[o2] = 0.f;
        }
#pragma unroll
        for (int o2 = 0; o2 < 16; o2++) t2s[h][o2] = out16[o2];
    }
    __syncthreads();

    int py = tid >> 4, px = tid & 15;
    u64 acc2[16];
#pragma unroll
    for (int i = 0; i < 16; i++) acc2[i] = 0ULL;
#pragma unroll 1
    for (int tap = 0; tap < 9; tap++) {
        int hh = (py + tap / 3) * 18 + (px + tap % 3);
        const float* src = &t2s[hh][0];
        u64 in2[8];
#pragma unroll
        for (int k = 0; k < 8; k++) in2[k] = f2pack(src[2 * k], src[2 * k + 1]);
        const u64* wt = &w3p[tap * 8];
#pragma unroll
        for (int oc = 0; oc < 16; oc++) {
            const u64* wr = wt + oc * 72;
#pragma unroll
            for (int k = 0; k < 8; k++) acc2[oc] = f2fma(in2[k], wr[k], acc2[oc]);
        }
    }
    float c3[16];
#pragma unroll
    for (int oc = 0; oc < 16; oc++) {
        float2 f = f2unpack(acc2[oc]);
        c3[oc] = fmaxf(f.x + f.y + b3[oc], 0.f);
    }
    u64 a2[8];
#pragma unroll
    for (int o2 = 0; o2 < 8; o2++) a2[o2] = f2pack(c3[2 * o2], c3[2 * o2 + 1]);
    int p = (ty0 + py) * 256 + tx0 + px;
    float* dst = t4 + (size_t)p * 32;
#pragma unroll
    for (int c4 = 0; c4 < 32; c4++) {
        u64 r = 0ULL;
#pragma unroll
        for (int o2 = 0; o2 < 8; o2++) r = f2fma(a2[o2], w4p[c4 * 8 + o2], r);
        float2 f = f2unpack(r);
        dst[c4] = f.x + f.y + b4[c4];
    }
}

// ---------------- K3a: instance-norm partial sums ----------------
__global__ __launch_bounds__(256) void inorm_part_kernel(const float* __restrict__ t4,
                                                         float* __restrict__ part) {
    int tid = threadIdx.x;
    size_t base = (size_t)blockIdx.x * 4096;
    float s[4] = {0, 0, 0, 0}, s2[4] = {0, 0, 0, 0};
    const float4* src = (const float4*)(t4 + base);
#pragma unroll
    for (int it = 0; it < 4; it++) {
        float4 v = src[it * 256 + tid];
        s[0] += v.x; s2[0] += v.x * v.x;
        s[1] += v.y; s2[1] += v.y * v.y;
        s[2] += v.z; s2[2] += v.z * v.z;
        s[3] += v.w; s2[3] += v.w * v.w;
    }
    __shared__ float sa[256][4], sb[256][4];
#pragma unroll
    for (int k = 0; k < 4; k++) { sa[tid][k] = s[k]; sb[tid][k] = s2[k]; }
    __syncthreads();
    if (tid < 32) {
        int grp = tid >> 2, k = tid & 3;
        float a = 0.f, b = 0.f;
#pragma unroll
        for (int t8 = 0; t8 < 32; t8++) {
            a += sa[t8 * 8 + grp][k];
            b += sb[t8 * 8 + grp][k];
        }
        part[blockIdx.x * 64 + tid] = a;
        part[blockIdx.x * 64 + 32 + tid] = b;
    }
}

// ---------------- K3b: instance-norm final reduce ----------------
__global__ __launch_bounds__(1024) void inorm_final_kernel(const float* __restrict__ part,
                                                           float* __restrict__ stats) {
    int tid = threadIdx.x;
    int c = tid & 31, g = tid >> 5;
    double a = 0.0, b = 0.0;
#pragma unroll
    for (int i = 0; i < 16; i++) {
        int blk = g * 16 + i;
        a += (double)part[blk * 64 + c];
        b += (double)part[blk * 64 + 32 + c];
    }
    __shared__ double sa[32][33], sb[32][33];
    sa[g][c] = a; sb[g][c] = b;
    __syncthreads();
    for (int o = 16; o; o >>= 1) {
        if (g < o) {
            sa[g][c] += sa[g + o][c];
            sb[g][c] += sb[g + o][c];
        }
        __syncthreads();
    }
    if (tid < 32) {
        double mean = sa[0][tid] / (double)HWP;
        double var = sb[0][tid] / (double)HWP - mean * mean;
        stats[tid] = (float)mean;
        stats[32 + tid] = rsqrtf((float)var + 1e-5f);
    }
}

// ---------------- K5: bias fragments ----------------
__global__ void build_biasF_kernel(const int* __restrict__ rpi, const float* __restrict__ rpb,
                                   u64* __restrict__ biasF) {
    int idx = blockIdx.x * 256 + threadIdx.x;
    int tig = idx & 3;
    int t2 = idx >> 2;
    int ch = t2 % 36;
    int t3 = t2 / 36;
    int q = t3 & 255;
    int h = t3 >> 8;
    int k0 = ch * 16 + 2 * tig;
    u64 r = 0;
#pragma unroll
    for (int e = 0; e < 4; e++) {
        int k = k0 + (e >> 1) * 8 + (e & 1);
        float v = rpb[rpi[q * NKEY + k] * 2 + h] * LOG2E;
        unsigned short us = __bfloat16_as_ushort(__float2bfloat16(v));
        r |= (u64)us << (16 * e);
    }
    biasF[idx] = r;
}

// ---------------- K6: LN once; weight-amortized projections ----------------
__global__ __launch_bounds__(256) void ln_qkv_kernel(
    const float* __restrict__ xhwc, const float* __restrict__ t4,
    const float* __restrict__ stats,
    const float* __restrict__ in_g, const float* __restrict__ in_b,
    const float* __restrict__ n1g, const float* __restrict__ n1b,
    const float* __restrict__ wq, const float* __restrict__ bq,
    const float* __restrict__ wkv, const float* __restrict__ bkv,
    __nv_bfloat16* __restrict__ qbase, __nv_bfloat16* __restrict__ kvbase) {
    __shared__ u64 s_wq2[512], s_wk2[512], s_wv2[512];
    __shared__ float s_bq[32], s_bkv[64], s_g[32], s_b[32], s_A[32], s_C[32];
    __shared__ __align__(16) float s_actx[8][PPW][32];
    __shared__ __align__(16) float s_actf[8][PPW][32];
    int tid = threadIdx.x;
    for (int idx = tid; idx < 512; idx += 256) {
        int i2 = idx >> 5, l = idx & 31;
        s_wq2[idx] = f2pack(wq[(2 * i2) * 32 + l], wq[(2 * i2 + 1) * 32 + l]);
        s_wk2[idx] = f2pack(wkv[(2 * i2) * 64 + l], wkv[(2 * i2 + 1) * 64 + l]);
        s_wv2[idx] = f2pack(wkv[(2 * i2) * 64 + 32 + l], wkv[(2 * i2 + 1) * 64 + 32 + l]);
    }
    if (tid < 32) {
        s_bq[tid] = bq[tid]; s_g[tid] = n1g[tid]; s_b[tid] = n1b[tid];
        float A = stats[32 + tid] * in_g[tid];
        s_A[tid] = A;
        s_C[tid] = in_b[tid] - stats[tid] * A;
    }
    if (tid < 64) s_bkv[tid] = bkv[tid];
    __syncthreads();
    __nv_bfloat16* q0  = qbase;
    __nv_bfloat16* q1  = qbase + (size_t)HWP * 32;
    __nv_bfloat16* kv0 = kvbase;
    __nv_bfloat16* kv1 = kvbase + (size_t)HWP * 64;
    int lane = tid & 31, w = tid >> 5;
    int pbase = blockIdx.x * (8 * PPW) + w * PPW;
    const float QS = 0.25f * LOG2E;

    // phase 1: LN for all PPW pixels
#pragma unroll 1
    for (int it = 0; it < PPW; it++) {
        int p = pbase + it;
        float xv = xhwc[p * 32 + lane];
        float fvv = t4[p * 32 + lane] * s_A[lane] + s_C[lane];
        float mx = warp_sum(xv) * (1.f / 32.f);
        float dx = xv - mx;
        float vx = warp_sum(dx * dx) * (1.f / 32.f);
        s_actx[w][it][lane] = dx * rsqrtf(vx + 1e-5f) * s_g[lane] + s_b[lane];
        float mf = warp_sum(fvv) * (1.f / 32.f);
        float df = fvv - mf;
        float vf = warp_sum(df * df) * (1.f / 32.f);
        s_actf[w][it][lane] = df * rsqrtf(vf + 1e-5f) * s_g[lane] + s_b[lane];
    }
    __syncwarp();

    // phase 2: weight-amortized projections, per side
#pragma unroll 1
    for (int side = 0; side < 2; side++) {
        const float* act = side ? &s_actf[w][0][0] : &s_actx[w][0][0];
        __nv_bfloat16* qo  = side ? q1 : q0;
        __nv_bfloat16* kvo = side ? kv0 : kv1;
        u64 aq[PPW], ak[PPW], av[PPW];
#pragma unroll
        for (int it = 0; it < PPW; it++) { aq[it] = 0ULL; ak[it] = 0ULL; av[it] = 0ULL; }
#pragma unroll
        for (int i2 = 0; i2 < 16; i2++) {
            u64 wqv = s_wq2[i2 * 32 + lane];
            u64 wkw = s_wk2[i2 * 32 + lane];
            u64 wvw = s_wv2[i2 * 32 + lane];
#pragma unroll
            for (int it = 0; it < PPW; it++) {
                u64 x2 = *(const u64*)&act[it * 32 + 2 * i2];
                aq[it] = f2fma(x2, wqv, aq[it]);
                ak[it] = f2fma(x2, wkw, ak[it]);
                av[it] = f2fma(x2, wvw, av[it]);
            }
        }
#pragma unroll
        for (int it = 0; it < PPW; it++) {
            int p = pbase + it;
            float2 fq = f2unpack(aq[it]), fk = f2unpack(ak[it]), fv2 = f2unpack(av[it]);
            qo[p * 32 + lane] = __float2bfloat16((fq.x + fq.y + s_bq[lane]) * QS);
            kvo[p * 64 + lane]      = __float2bfloat16(fk.x + fk.y + s_bkv[lane]);
            kvo[p * 64 + 32 + lane] = __float2bfloat16(fv2.x + fv2.y + s_bkv[lane + 32]);
        }
    }
}

// ---------------- K7: flash attention, both z per block (bias loads shared) ----------------
__global__ __launch_bounds__(256) void attn_kernel(
    const __nv_bfloat16* __restrict__ qbase, const __nv_bfloat16* __restrict__ kvbase,
    const u64* __restrict__ biasF, __nv_bfloat16* __restrict__ outbase) {
    extern __shared__ __align__(16) char smraw[];
    int win = blockIdx.x, head = blockIdx.y;
    int wy = win >> 4, wx = win & 15;
    int t = threadIdx.x;
    int warp = t >> 5, lane = t & 31;
    int gid = lane >> 2, tig = lane & 3;

    __nv_bfloat16* ksmz[2] = {(__nv_bfloat16*)smraw, (__nv_bfloat16*)(smraw + KBYTES)};
    __nv_bfloat16* vsmz[2] = {(__nv_bfloat16*)(smraw + 2 * KBYTES),
                              (__nv_bfloat16*)(smraw + 2 * KBYTES + VBYTES)};

    for (int j = t; j < NKEY; j += 256) {
        int jy = j / 24, jx = j - jy * 24;
        int yy = (wy << 4) - 4 + jy, xx = (wx << 4) - 4 + jx;
        bool inb = ((unsigned)yy < 256u && (unsigned)xx < 256u);
#pragma unroll
        for (int z = 0; z < 2; z++) {
            uint4 k0 = make_uint4(0, 0, 0, 0), k1 = k0, v0 = k0, v1 = k0;
            if (inb) {
                const __nv_bfloat16* base = kvbase + (size_t)z * HWP * 64 +
                                            ((size_t)((yy << 8) + xx) << 6) + (head << 4);
                k0 = *(const uint4*)base;
                k1 = *(const uint4*)(base + 8);
                v0 = *(const uint4*)(base + 32);
                v1 = *(const uint4*)(base + 40);
            }
            *(uint4*)(ksmz[z] + j * KSTRIDE)     = k0;
            *(uint4*)(ksmz[z] + j * KSTRIDE + 8) = k1;
            u32 vw[8] = {v0.x, v0.y, v0.z, v0.w, v1.x, v1.y, v1.z, v1.w};
#pragma unroll
            for (int i = 0; i < 8; i++) {
                __nv_bfloat162 pr = *(const __nv_bfloat162*)&vw[i];
                vsmz[z][(2 * i) * VSTRIDE + j]     = pr.x;
                vsmz[z][(2 * i + 1) * VSTRIDE + j] = pr.y;
            }
        }
    }

    u32 qa[2][2][4];
    int qwb = warp * 32;
#pragma unroll
    for (int z = 0; z < 2; z++) {
        const __nv_bfloat16* q = qbase + (size_t)z * HWP * 32;
#pragma unroll
        for (int m = 0; m < 2; m++) {
            int r0 = qwb + m * 16 + gid;
            int r1 = r0 + 8;
            int px0 = ((wy << 4) + (r0 >> 4)) * 256 + (wx << 4) + (r0 & 15);
            int px1 = ((wy << 4) + (r1 >> 4)) * 256 + (wx << 4) + (r1 & 15);
            const __nv_bfloat16* q0p = q + (size_t)px0 * 32 + (head << 4);
            const __nv_bfloat16* q1p = q + (size_t)px1 * 32 + (head << 4);
            qa[z][m][0] = *(const u32*)(q0p + 2 * tig);
            qa[z][m][1] = *(const u32*)(q1p + 2 * tig);
            qa[z][m][2] = *(const u32*)(q0p + 8 + 2 * tig);
            qa[z][m][3] = *(const u32*)(q1p + 8 + 2 * tig);
        }
    }
    __syncthreads();

    float o[2][2][2][4];
#pragma unroll
    for (int z = 0; z < 2; z++)
#pragma unroll
        for (int m = 0; m < 2; m++)
#pragma unroll
            for (int d = 0; d < 2; d++)
#pragma unroll
                for (int i = 0; i < 4; i++) o[z][m][d][i] = 0.f;
    float l4[2][4] = {{0.f, 0.f, 0.f, 0.f}, {0.f, 0.f, 0.f, 0.f}};

    const u64* bF = biasF + ((size_t)head << 8) * 144;

#pragma unroll 1
    for (int ch = 0; ch < 36; ch++) {
        int kb = ch * 16;
        u64 bw[4];
#pragma unroll
        for (int r4 = 0; r4 < 4; r4++) {
            int qrow = qwb + ((r4 >> 1) << 4) + ((r4 & 1) << 3) + gid;
            bw[r4] = bF[(qrow * 36 + ch) * 4 + tig];
        }
#pragma unroll
        for (int z = 0; z < 2; z++) {
            u32 kf[2][2];
#pragma unroll
            for (int nt = 0; nt < 2; nt++) {
                const __nv_bfloat16* kr = ksmz[z] + (kb + nt * 8 + gid) * KSTRIDE + 2 * tig;
                kf[nt][0] = *(const u32*)kr;
                kf[nt][1] = *(const u32*)(kr + 8);
            }
            u32 vb[2][2];
#pragma unroll
            for (int dt = 0; dt < 2; dt++) {
                const __nv_bfloat16* vr = vsmz[z] + (dt * 8 + gid) * VSTRIDE + kb + 2 * tig;
                vb[dt][0] = *(const u32*)vr;
                vb[dt][1] = *(const u32*)(vr + 8);
            }
#pragma unroll
            for (int m = 0; m < 2; m++) {
                float c0[4] = {0.f, 0.f, 0.f, 0.f}, c1[4] = {0.f, 0.f, 0.f, 0.f};
                mma_bf16(c0, qa[z][m], kf[0], c0);
                mma_bf16(c1, qa[z][m], kf[1], c1);
                u32 bAlo = (u32)bw[m * 2],     bAhi = (u32)(bw[m * 2] >> 32);
                u32 bBlo = (u32)bw[m * 2 + 1], bBhi = (u32)(bw[m * 2 + 1] >> 32);
                float p00 = ex2f(fminf(c0[0] + __int_as_float(bAlo << 16), 80.f));
                float p01 = ex2f(fminf(c0[1] + __int_as_float((int)(bAlo & 0xffff0000u)), 80.f));
                float p02 = ex2f(fminf(c0[2] + __int_as_float(bBlo << 16), 80.f));
                float p03 = ex2f(fminf(c0[3] + __int_as_float((int)(bBlo & 0xffff0000u)), 80.f));
                float p10 = ex2f(fminf(c1[0] + __int_as_float(bAhi << 16), 80.f));
                float p11 = ex2f(fminf(c1[1] + __int_as_float((int)(bAhi & 0xffff0000u)), 80.f));
                float p12 = ex2f(fminf(c1[2] + __int_as_float(bBhi << 16), 80.f));
                float p13 = ex2f(fminf(c1[3] + __int_as_float((int)(bBhi & 0xffff0000u)), 80.f));
                l4[z][m * 2]     += (p00 + p01) + (p10 + p11);
                l4[z][m * 2 + 1] += (p02 + p03) + (p12 + p13);
                u32 pa[4];
                pa[0] = bfpack(p00, p01);
                pa[1] = bfpack(p02, p03);
                pa[2] = bfpack(p10, p11);
                pa[3] = bfpack(p12, p13);
                mma_bf16(o[z][m][0], pa, vb[0], o[z][m][0]);
                mma_bf16(o[z][m][1], pa, vb[1], o[z][m][1]);
            }
        }
    }

#pragma unroll
    for (int z = 0; z < 2; z++)
#pragma unroll
        for (int r4 = 0; r4 < 4; r4++) {
            l4[z][r4] += __shfl_xor_sync(0xffffffffu, l4[z][r4], 1);
            l4[z][r4] += __shfl_xor_sync(0xffffffffu, l4[z][r4], 2);
            l4[z][r4] = 1.f / l4[z][r4];
        }

#pragma unroll
    for (int z = 0; z < 2; z++) {
        __nv_bfloat16* out = outbase + (size_t)z * HWP * 32;
#pragma unroll
        for (int m = 0; m < 2; m++) {
            int r0 = qwb + m * 16 + gid;
            int r1 = r0 + 8;
            int px0 = ((wy << 4) + (r0 >> 4)) * 256 + (wx << 4) + (r0 & 15);
            int px1 = ((wy << 4) + (r1 >> 4)) * 256 + (wx << 4) + (r1 & 15);
            __nv_bfloat16* o0p = out + (size_t)px0 * 32 + (head << 4);
            __nv_bfloat16* o1p = out + (size_t)px1 * 32 + (head << 4);
            float i0 = l4[z][m * 2], i1 = l4[z][m * 2 + 1];
#pragma unroll
            for (int dt = 0; dt < 2; dt++) {
                *(u32*)(o0p + dt * 8 + 2 * tig) =
                    bfpack(o[z][m][dt][0] * i0, o[z][m][dt][1] * i0);
                *(u32*)(o1p + dt * 8 + 2 * tig) =
                    bfpack(o[z][m][dt][2] * i1, o[z][m][dt][3] * i1);
            }
        }
    }
}

// ---------------- K8: both OCAB tails + final sum + HWC->CHW, fused ----------------
__global__ __launch_bounds__(256) void proj_mlp_kernel(
    const __nv_bfloat16* __restrict__ attbase,
    const float* __restrict__ xhwc, const float* __restrict__ t4,
    const float* __restrict__ x_chw,
    const float* __restrict__ stats,
    const float* __restrict__ in_g, const float* __restrict__ in_b,
    const float* __restrict__ wp, const float* __restrict__ bp,
    const float* __restrict__ n2g, const float* __restrict__ n2b,
    const float* __restrict__ mw1, const float* __restrict__ mb1,
    const float* __restrict__ mw2, const float* __restrict__ mb2,
    float* __restrict__ out) {
    __shared__ u64 s_wp2[512], s_m1a[512], s_m1b[512], s_m2[1024];
    __shared__ float s_bp[32], s_mb1[64], s_mb2[32], s_g[32], s_b[32], s_A[32], s_C[32];
    __shared__ __align__(16) float s_act[8][32];
    __shared__ __align__(16) float s_h[8][64];
    __shared__ float s_o[64][33];
    int tid = threadIdx.x;
    for (int idx = tid; idx < 512; idx += 256) {
        int i2 = idx >> 5, l = idx & 31;
        s_wp2[idx] = f2pack(wp[(2 * i2) * 32 + l], wp[(2 * i2 + 1) * 32 + l]);
        s_m1a[idx] = f2pack(mw1[(2 * i2) * 64 + l], mw1[(2 * i2 + 1) * 64 + l]);
        s_m1b[idx] = f2pack(mw1[(2 * i2) * 64 + 32 + l], mw1[(2 * i2 + 1) * 64 + 32 + l]);
    }
    for (int idx = tid; idx < 1024; idx += 256) {
        int i2 = idx >> 5, l = idx & 31;
        s_m2[idx] = f2pack(mw2[(2 * i2) * 32 + l], mw2[(2 * i2 + 1) * 32 + l]);
    }
    if (tid < 32) {
        s_bp[tid] = bp[tid]; s_mb2[tid] = mb2[tid]; s_g[tid] = n2g[tid]; s_b[tid] = n2b[tid];
        float A = stats[32 + tid] * in_g[tid];
        s_A[tid] = A;
        s_C[tid] = in_b[tid] - stats[tid] * A;
    }
    if (tid < 64) s_mb1[tid] = mb1[tid];
    __syncthreads();
    int lane = tid & 31, w = tid >> 5;
    int p0blk = blockIdx.x * 64;
    int pbase = p0blk + w * PPW;

#pragma unroll 1
    for (int it = 0; it < PPW; it++) {
        int p = pbase + it;
        float xv = xhwc[p * 32 + lane];
        float fvv = t4[p * 32 + lane] * s_A[lane] + s_C[lane];
        float osum = 0.f;
#pragma unroll 1
        for (int z = 0; z < 2; z++) {
            float scv = z ? fvv : xv;
            float a = __bfloat162float(attbase[(size_t)z * HWP * 32 + p * 32 + lane]);
            s_act[w][lane] = a;
            __syncwarp();
            u64 acc = 0ULL;
#pragma unroll
            for (int i2 = 0; i2 < 16; i2++) {
                u64 x2 = *(const u64*)&s_act[w][2 * i2];
                acc = f2fma(x2, s_wp2[i2 * 32 + lane], acc);
            }
            float2 fy = f2unpack(acc);
            float y = fy.x + fy.y + s_bp[lane] + scv;

            float mean = warp_sum(y) * (1.f / 32.f);
            float dv = y - mean;
            float var = warp_sum(dv * dv) * (1.f / 32.f);
            float yn = dv * rsqrtf(var + 1e-5f) * s_g[lane] + s_b[lane];

            __syncwarp();
            s_act[w][lane] = yn;
            __syncwarp();
            u64 h0a = 0ULL, h1a = 0ULL;
#pragma unroll
            for (int i2 = 0; i2 < 16; i2++) {
                u64 x2 = *(const u64*)&s_act[w][2 * i2];
                h0a = f2fma(x2, s_m1a[i2 * 32 + lane], h0a);
                h1a = f2fma(x2, s_m1b[i2 * 32 + lane], h1a);
            }
            float2 f0 = f2unpack(h0a), f1 = f2unpack(h1a);
            float h0 = gelu_tanh(f0.x + f0.y + s_mb1[lane]);
            float h1 = gelu_tanh(f1.x + f1.y + s_mb1[lane + 32]);
            s_h[w][lane] = h0;
            s_h[w][32 + lane] = h1;
            __syncwarp();
            u64 r2 = 0ULL;
#pragma unroll
            for (int i2 = 0; i2 < 32; i2++) {
                u64 g2 = *(const u64*)&s_h[w][2 * i2];
                r2 = f2fma(g2, s_m2[i2 * 32 + lane], r2);
            }
            float2 fr = f2unpack(r2);
            osum += y + fr.x + fr.y + s_mb2[lane];
            __syncwarp();
        }
        s_o[w * PPW + it][lane] = osum;
    }
    __syncthreads();
#pragma unroll
    for (int e = tid; e < 2048; e += 256) {
        int c = e >> 6, px = e & 63;
        int gp = p0blk + px;
        out[c * HWP + gp] = s_o[px][c] + x_chw[c * HWP + gp];
    }
}

// ---------------- launch ----------------
extern "C" void kernel_launch(void* const* d_in, const int* in_sizes, int n_in,
                              void* d_out, int out_size) {
    const float* x    = (const float*)d_in[0];
    const float* dep  = (const float*)d_in[1];
    const int*   rpi  = (const int*)  d_in[2];
    const float* cw1  = (const float*)d_in[3];
    const float* cb1  = (const float*)d_in[4];
    const float* cw2  = (const float*)d_in[5];
    const float* cb2  = (const float*)d_in[6];
    const float* cw3  = (const float*)d_in[7];
    const float* cb3  = (const float*)d_in[8];
    const float* cw4  = (const float*)d_in[9];
    const float* cb4  = (const float*)d_in[10];
    const float* in_g = (const float*)d_in[11];
    const float* in_b = (const float*)d_in[12];
    const float* n1g  = (const float*)d_in[13];
    const float* n1b  = (const float*)d_in[14];
    const float* wq   = (const float*)d_in[15];
    const float* bq   = (const float*)d_in[16];
    const float* wkv  = (const float*)d_in[17];
    const float* bkv  = (const float*)d_in[18];
    const float* rpb  = (const float*)d_in[19];
    const float* wp   = (const float*)d_in[20];
    const float* bp   = (const float*)d_in[21];
    const float* n2g  = (const float*)d_in[22];
    const float* n2b  = (const float*)d_in[23];
    const float* mw1  = (const float*)d_in[24];
    const float* mb1  = (const float*)d_in[25];
    const float* mw2  = (const float*)d_in[26];
    const float* mb2  = (const float*)d_in[27];
    float* out = (float*)d_out;

    void *p_xhwc, *p_t4, *p_q, *p_kv, *p_att, *p_bias, *p_stats, *p_part;
    cudaGetSymbolAddress(&p_xhwc, g_xhwc);
    cudaGetSymbolAddress(&p_t4, g_t4);
    cudaGetSymbolAddress(&p_q, g_qbf);
    cudaGetSymbolAddress(&p_kv, g_kvbf);
    cudaGetSymbolAddress(&p_att, g_attbf);
    cudaGetSymbolAddress(&p_bias, g_biasF);
    cudaGetSymbolAddress(&p_stats, g_stats);
    cudaGetSymbolAddress(&p_part, g_part);

    cudaFuncSetAttribute(attn_kernel, cudaFuncAttributeMaxDynamicSharedMemorySize, SMEM_ATTN);

    chw2hwc_kernel<<<2048, dim3(32, 8)>>>(x, (float*)p_xhwc);
    stem_fused_kernel<<<256, 256>>>(dep, cw1, cb1, cw2, cb2, cw3, cb3, cw4, cb4,
                                    (float*)p_t4);
    inorm_part_kernel<<<512, 256>>>((float*)p_t4, (float*)p_part);
    inorm_final_kernel<<<1, 1024>>>((float*)p_part, (float*)p_stats);
    build_biasF_kernel<<<288, 256>>>(rpi, rpb, (u64*)p_bias);

    ln_qkv_kernel<<<HWP / (8 * PPW), 256>>>(
        (float*)p_xhwc, (float*)p_t4, (float*)p_stats, in_g, in_b, n1g, n1b,
        wq, bq, wkv, bkv, (__nv_bfloat16*)p_q, (__nv_bfloat16*)p_kv);
    attn_kernel<<<dim3(NWIN, 2), 256, SMEM_ATTN>>>((__nv_bfloat16*)p_q,
                                                   (__nv_bfloat16*)p_kv,
                                                   (u64*)p_bias,
                                                   (__nv_bfloat16*)p_att);
    proj_mlp_kernel<<<HWP / 64, 256>>>(
        (__nv_bfloat16*)p_att, (float*)p_xhwc, (float*)p_t4, x, (float*)p_stats,
        in_g, in_b, wp, bp, n2g, n2b, mw1, mb1, mw2, mb2, out);
}

// round 14
// speedup vs baseline: 1.1910x; 1.0769x over previous
#include <cuda_runtime.h>
#include <cuda_bf16.h>
#include <math.h>

// Problem constants: B=1, C=32, H=W=256, WS=16, OWS=24, NH=2, d=16
#define HWP   65536
#define NKEY  576
#define NQ    256
#define NWIN  256

typedef unsigned long long u64;
typedef unsigned int u32;

#define LOG2E 1.4426950408889634f

// attn smem layout (both z resident)
#define KSTRIDE 24
#define VSTRIDE 584
#define KBYTES (NKEY * KSTRIDE * 2)          // 27648
#define VBYTES (16 * VSTRIDE * 2)            // 18688
#define SMEM_ATTN (2 * KBYTES + 2 * VBYTES)  // 92672

#define PPW 8

// ---------------- scratch ----------------
__device__ float          g_xhwc [HWP * 32];
__device__ float          g_t4   [HWP * 32];
__device__ __nv_bfloat16  g_qbf  [2 * HWP * 32];
__device__ __nv_bfloat16  g_kvbf [2 * HWP * 64];
__device__ __nv_bfloat16  g_attbf[2 * HWP * 32];
__device__ u64            g_biasF[2 * NQ * 36 * 4];
__device__ float          g_stats[64];
__device__ float          g_part [512 * 64];

// ---------------- helpers ----------------
__device__ __forceinline__ u64 f2pack(float lo, float hi) {
    u64 r; asm("mov.b64 %0, {%1, %2};" : "=l"(r) : "f"(lo), "f"(hi)); return r;
}
__device__ __forceinline__ float2 f2unpack(u64 v) {
    float2 f; asm("mov.b64 {%0, %1}, %2;" : "=f"(f.x), "=f"(f.y) : "l"(v)); return f;
}
__device__ __forceinline__ u64 f2fma(u64 a, u64 b, u64 c) {
    u64 d; asm("fma.rn.f32x2 %0, %1, %2, %3;" : "=l"(d) : "l"(a), "l"(b), "l"(c)); return d;
}
__device__ __forceinline__ float ex2f(float x) {
    float y; asm("ex2.approx.f32 %0, %1;" : "=f"(y) : "f"(x)); return y;
}
__device__ __forceinline__ u32 bfpack(float lo, float hi) {
    u32 d; asm("cvt.rn.bf16x2.f32 %0, %1, %2;" : "=r"(d) : "f"(hi), "f"(lo)); return d;
}
__device__ __forceinline__ float warp_sum(float v) {
#pragma unroll
    for (int o = 16; o; o >>= 1) v += __shfl_xor_sync(0xffffffffu, v, o);
    return v;
}
__device__ __forceinline__ float gelu_tanh(float x) {
    float z = 0.7978845608028654f * (x + 0.044715f * x * x * x);
    float e = ex2f(2.8853900817779268f * z);
    float t = 1.f - __fdividef(2.f, e + 1.f);
    return 0.5f * x * (1.f + t);
}
__device__ __forceinline__ void mma_bf16(float* d, const u32* a, const u32* b, const float* c) {
    asm("mma.sync.aligned.m16n8k16.row.col.f32.bf16.bf16.f32 "
        "{%0,%1,%2,%3}, {%4,%5,%6,%7}, {%8,%9}, {%10,%11,%12,%13};"
        : "=f"(d[0]), "=f"(d[1]), "=f"(d[2]), "=f"(d[3])
        : "r"(a[0]), "r"(a[1]), "r"(a[2]), "r"(a[3]),
          "r"(b[0]), "r"(b[1]),
          "f"(c[0]), "f"(c[1]), "f"(c[2]), "f"(c[3]));
}

// ---------------- K0: CHW -> HWC transpose of x ----------------
__global__ void chw2hwc_kernel(const float* __restrict__ x, float* __restrict__ xh) {
    __shared__ float sm[32][33];
    int p0 = blockIdx.x * 32;
    int tx = threadIdx.x, ty = threadIdx.y;
    for (int c = ty; c < 32; c += 8) sm[c][tx] = x[c * HWP + p0 + tx];
    __syncthreads();
    for (int r = ty; r < 32; r += 8) xh[(p0 + r) * 32 + tx] = sm[tx][r];
}

// ---------------- K1: fused stem ----------------
__global__ __launch_bounds__(256) void stem_fused_kernel(
    const float* __restrict__ depth,
    const float* __restrict__ cw1, const float* __restrict__ cb1,
    const float* __restrict__ cw2, const float* __restrict__ cb2,
    const float* __restrict__ cw3, const float* __restrict__ cb3,
    const float* __restrict__ cw4, const float* __restrict__ cb4,
    float* __restrict__ t4) {
    __shared__ float w1[72], b1s[8], w2[128], b2s[16];
    __shared__ u64 w3p[1152];
    __shared__ u64 w4p[256];
    __shared__ float b3[16], b4[32];
    __shared__ float t2s[324][17];
    int tid = threadIdx.x;
    if (tid < 72)  w1[tid]  = cw1[tid];
    if (tid < 8)   b1s[tid] = cb1[tid];
    if (tid < 128) w2[tid]  = cw2[tid];
    if (tid < 16)  b2s[tid] = cb2[tid];
    for (int i = tid; i < 1152; i += 256) {
        int oc = i / 72, r = i - oc * 72, tap = r >> 3, ic2 = r & 7;
        w3p[i] = f2pack(cw3[oc * 144 + (2 * ic2) * 9 + tap],
                        cw3[oc * 144 + (2 * ic2 + 1) * 9 + tap]);
    }
    if (tid < 256) {
        int c4 = tid >> 3, o2 = tid & 7;
        w4p[tid] = f2pack(cw4[c4 * 16 + 2 * o2], cw4[c4 * 16 + 2 * o2 + 1]);
    }
    if (tid < 16) b3[tid] = cb3[tid];
    if (tid < 32) b4[tid] = cb4[tid];
    __syncthreads();

    int ty0 = (blockIdx.x >> 4) << 4;
    int tx0 = (blockIdx.x & 15) << 4;

    for (int h = tid; h < 324; h += 256) {
        int hy = h / 18, hx = h - hy * 18;
        int gy = ty0 + hy - 1, gx = tx0 + hx - 1;
        float out16[16];
        if ((unsigned)gy < 256u && (unsigned)gx < 256u) {
            float d[9];
#pragma unroll
            for (int tap = 0; tap < 9; tap++) {
                int yy = gy + tap / 3 - 1, xx = gx + tap % 3 - 1;
                d[tap] = ((unsigned)yy < 256u && (unsigned)xx < 256u)
                             ? depth[(yy << 8) + xx] : 0.f;
            }
            float c1[8];
#pragma unroll
            for (int o = 0; o < 8; o++) {
                float a = b1s[o];
#pragma unroll
                for (int tap = 0; tap < 9; tap++) a += d[tap] * w1[o * 9 + tap];
                c1[o] = fmaxf(a, 0.f);
            }
#pragma unroll
            for (int o2 = 0; o2 < 16; o2++) {
                float a = b2s[o2];
#pragma unroll
                for (int o = 0; o < 8; o++) a += c1[o] * w2[o2 * 8 + o];
                out16[o2] = fmaxf(a, 0.f);
            }
        } else {
#pragma unroll
            for (int o2 = 0; o2 < 16; o2++) out16[o2] = 0.f;
        }
#pragma unroll
        for (int o2 = 0; o2 < 16; o2++) t2s[h][o2] = out16[o2];
    }
    __syncthreads();

    int py = tid >> 4, px = tid & 15;
    u64 acc2[16];
#pragma unroll
    for (int i = 0; i < 16; i++) acc2[i] = 0ULL;
#pragma unroll 1
    for (int tap = 0; tap < 9; tap++) {
        int hh = (py + tap / 3) * 18 + (px + tap % 3);
        const float* src = &t2s[hh][0];
        u64 in2[8];
#pragma unroll
        for (int k = 0; k < 8; k++) in2[k] = f2pack(src[2 * k], src[2 * k + 1]);
        const u64* wt = &w3p[tap * 8];
#pragma unroll
        for (int oc = 0; oc < 16; oc++) {
            const u64* wr = wt + oc * 72;
#pragma unroll
            for (int k = 0; k < 8; k++) acc2[oc] = f2fma(in2[k], wr[k], acc2[oc]);
        }
    }
    float c3[16];
#pragma unroll
    for (int oc = 0; oc < 16; oc++) {
        float2 f = f2unpack(acc2[oc]);
        c3[oc] = fmaxf(f.x + f.y + b3[oc], 0.f);
    }
    u64 a2[8];
#pragma unroll
    for (int o2 = 0; o2 < 8; o2++) a2[o2] = f2pack(c3[2 * o2], c3[2 * o2 + 1]);
    int p = (ty0 + py) * 256 + tx0 + px;
    float* dst = t4 + (size_t)p * 32;
#pragma unroll
    for (int c4 = 0; c4 < 32; c4++) {
        u64 r = 0ULL;
#pragma unroll
        for (int o2 = 0; o2 < 8; o2++) r = f2fma(a2[o2], w4p[c4 * 8 + o2], r);
        float2 f = f2unpack(r);
        dst[c4] = f.x + f.y + b4[c4];
    }
}

// ---------------- K3a: instance-norm partial sums ----------------
__global__ __launch_bounds__(256) void inorm_part_kernel(const float* __restrict__ t4,
                                                         float* __restrict__ part) {
    int tid = threadIdx.x;
    size_t base = (size_t)blockIdx.x * 4096;
    float s[4] = {0, 0, 0, 0}, s2[4] = {0, 0, 0, 0};
    const float4* src = (const float4*)(t4 + base);
#pragma unroll
    for (int it = 0; it < 4; it++) {
        float4 v = src[it * 256 + tid];
        s[0] += v.x; s2[0] += v.x * v.x;
        s[1] += v.y; s2[1] += v.y * v.y;
        s[2] += v.z; s2[2] += v.z * v.z;
        s[3] += v.w; s2[3] += v.w * v.w;
    }
    __shared__ float sa[256][4], sb[256][4];
#pragma unroll
    for (int k = 0; k < 4; k++) { sa[tid][k] = s[k]; sb[tid][k] = s2[k]; }
    __syncthreads();
    if (tid < 32) {
        int grp = tid >> 2, k = tid & 3;
        float a = 0.f, b = 0.f;
#pragma unroll
        for (int t8 = 0; t8 < 32; t8++) {
            a += sa[t8 * 8 + grp][k];
            b += sb[t8 * 8 + grp][k];
        }
        part[blockIdx.x * 64 + tid] = a;
        part[blockIdx.x * 64 + 32 + tid] = b;
    }
}

// ---------------- K3b: instance-norm final reduce ----------------
__global__ __launch_bounds__(1024) void inorm_final_kernel(const float* __restrict__ part,
                                                           float* __restrict__ stats) {
    int tid = threadIdx.x;
    int c = tid & 31, g = tid >> 5;
    double a = 0.0, b = 0.0;
#pragma unroll
    for (int i = 0; i < 16; i++) {
        int blk = g * 16 + i;
        a += (double)part[blk * 64 + c];
        b += (double)part[blk * 64 + 32 + c];
    }
    __shared__ double sa[32][33], sb[32][33];
    sa[g][c] = a; sb[g][c] = b;
    __syncthreads();
    for (int o = 16; o; o >>= 1) {
        if (g < o) {
            sa[g][c] += sa[g + o][c];
            sb[g][c] += sb[g + o][c];
        }
        __syncthreads();
    }
    if (tid < 32) {
        double mean = sa[0][tid] / (double)HWP;
        double var = sb[0][tid] / (double)HWP - mean * mean;
        stats[tid] = (float)mean;
        stats[32 + tid] = rsqrtf((float)var + 1e-5f);
    }
}

// ---------------- K5: bias fragments ----------------
__global__ void build_biasF_kernel(const int* __restrict__ rpi, const float* __restrict__ rpb,
                                   u64* __restrict__ biasF) {
    int idx = blockIdx.x * 256 + threadIdx.x;
    int tig = idx & 3;
    int t2 = idx >> 2;
    int ch = t2 % 36;
    int t3 = t2 / 36;
    int q = t3 & 255;
    int h = t3 >> 8;
    int k0 = ch * 16 + 2 * tig;
    u64 r = 0;
#pragma unroll
    for (int e = 0; e < 4; e++) {
        int k = k0 + (e >> 1) * 8 + (e & 1);
        float v = rpb[rpi[q * NKEY + k] * 2 + h] * LOG2E;
        unsigned short us = __bfloat16_as_ushort(__float2bfloat16(v));
        r |= (u64)us << (16 * e);
    }
    biasF[idx] = r;
}

// ---------------- K6: LN once; weight-amortized projections ----------------
__global__ __launch_bounds__(256) void ln_qkv_kernel(
    const float* __restrict__ xhwc, const float* __restrict__ t4,
    const float* __restrict__ stats,
    const float* __restrict__ in_g, const float* __restrict__ in_b,
    const float* __restrict__ n1g, const float* __restrict__ n1b,
    const float* __restrict__ wq, const float* __restrict__ bq,
    const float* __restrict__ wkv, const float* __restrict__ bkv,
    __nv_bfloat16* __restrict__ qbase, __nv_bfloat16* __restrict__ kvbase) {
    __shared__ u64 s_wq2[512], s_wk2[512], s_wv2[512];
    __shared__ float s_bq[32], s_bkv[64], s_g[32], s_b[32], s_A[32], s_C[32];
    __shared__ __align__(16) float s_actx[8][PPW][32];
    __shared__ __align__(16) float s_actf[8][PPW][32];
    int tid = threadIdx.x;
    for (int idx = tid; idx < 512; idx += 256) {
        int i2 = idx >> 5, l = idx & 31;
        s_wq2[idx] = f2pack(wq[(2 * i2) * 32 + l], wq[(2 * i2 + 1) * 32 + l]);
        s_wk2[idx] = f2pack(wkv[(2 * i2) * 64 + l], wkv[(2 * i2 + 1) * 64 + l]);
        s_wv2[idx] = f2pack(wkv[(2 * i2) * 64 + 32 + l], wkv[(2 * i2 + 1) * 64 + 32 + l]);
    }
    if (tid < 32) {
        s_bq[tid] = bq[tid]; s_g[tid] = n1g[tid]; s_b[tid] = n1b[tid];
        float A = stats[32 + tid] * in_g[tid];
        s_A[tid] = A;
        s_C[tid] = in_b[tid] - stats[tid] * A;
    }
    if (tid < 64) s_bkv[tid] = bkv[tid];
    __syncthreads();
    __nv_bfloat16* q0  = qbase;
    __nv_bfloat16* q1  = qbase + (size_t)HWP * 32;
    __nv_bfloat16* kv0 = kvbase;
    __nv_bfloat16* kv1 = kvbase + (size_t)HWP * 64;
    int lane = tid & 31, w = tid >> 5;
    int pbase = blockIdx.x * (8 * PPW) + w * PPW;
    const float QS = 0.25f * LOG2E;

#pragma unroll 1
    for (int it = 0; it < PPW; it++) {
        int p = pbase + it;
        float xv = xhwc[p * 32 + lane];
        float fvv = t4[p * 32 + lane] * s_A[lane] + s_C[lane];
        float mx = warp_sum(xv) * (1.f / 32.f);
        float dx = xv - mx;
        float vx = warp_sum(dx * dx) * (1.f / 32.f);
        s_actx[w][it][lane] = dx * rsqrtf(vx + 1e-5f) * s_g[lane] + s_b[lane];
        float mf = warp_sum(fvv) * (1.f / 32.f);
        float df = fvv - mf;
        float vf = warp_sum(df * df) * (1.f / 32.f);
        s_actf[w][it][lane] = df * rsqrtf(vf + 1e-5f) * s_g[lane] + s_b[lane];
    }
    __syncwarp();

#pragma unroll 1
    for (int side = 0; side < 2; side++) {
        const float* act = side ? &s_actf[w][0][0] : &s_actx[w][0][0];
        __nv_bfloat16* qo  = side ? q1 : q0;
        __nv_bfloat16* kvo = side ? kv0 : kv1;
        u64 aq[PPW], ak[PPW], av[PPW];
#pragma unroll
        for (int it = 0; it < PPW; it++) { aq[it] = 0ULL; ak[it] = 0ULL; av[it] = 0ULL; }
#pragma unroll
        for (int i2 = 0; i2 < 16; i2++) {
            u64 wqv = s_wq2[i2 * 32 + lane];
            u64 wkw = s_wk2[i2 * 32 + lane];
            u64 wvw = s_wv2[i2 * 32 + lane];
#pragma unroll
            for (int it = 0; it < PPW; it++) {
                u64 x2 = *(const u64*)&act[it * 32 + 2 * i2];
                aq[it] = f2fma(x2, wqv, aq[it]);
                ak[it] = f2fma(x2, wkw, ak[it]);
                av[it] = f2fma(x2, wvw, av[it]);
            }
        }
#pragma unroll
        for (int it = 0; it < PPW; it++) {
            int p = pbase + it;
            float2 fq = f2unpack(aq[it]), fk = f2unpack(ak[it]), fv2 = f2unpack(av[it]);
            qo[p * 32 + lane] = __float2bfloat16((fq.x + fq.y + s_bq[lane]) * QS);
            kvo[p * 64 + lane]      = __float2bfloat16(fk.x + fk.y + s_bkv[lane]);
            kvo[p * 64 + 32 + lane] = __float2bfloat16(fv2.x + fv2.y + s_bkv[lane + 32]);
        }
    }
}

// ---------------- K7: flash attention, both z per block (bias loads shared) ----------------
__global__ __launch_bounds__(256) void attn_kernel(
    const __nv_bfloat16* __restrict__ qbase, const __nv_bfloat16* __restrict__ kvbase,
    const u64* __restrict__ biasF, __nv_bfloat16* __restrict__ outbase) {
    extern __shared__ __align__(16) char smraw[];
    int win = blockIdx.x, head = blockIdx.y;
    int wy = win >> 4, wx = win & 15;
    int t = threadIdx.x;
    int warp = t >> 5, lane = t & 31;
    int gid = lane >> 2, tig = lane & 3;

    __nv_bfloat16* ksmz[2] = {(__nv_bfloat16*)smraw, (__nv_bfloat16*)(smraw + KBYTES)};
    __nv_bfloat16* vsmz[2] = {(__nv_bfloat16*)(smraw + 2 * KBYTES),
                              (__nv_bfloat16*)(smraw + 2 * KBYTES + VBYTES)};

    for (int j = t; j < NKEY; j += 256) {
        int jy = j / 24, jx = j - jy * 24;
        int yy = (wy << 4) - 4 + jy, xx = (wx << 4) - 4 + jx;
        bool inb = ((unsigned)yy < 256u && (unsigned)xx < 256u);
#pragma unroll
        for (int z = 0; z < 2; z++) {
            uint4 k0 = make_uint4(0, 0, 0, 0), k1 = k0, v0 = k0, v1 = k0;
            if (inb) {
                const __nv_bfloat16* base = kvbase + (size_t)z * HWP * 64 +
                                            ((size_t)((yy << 8) + xx) << 6) + (head << 4);
                k0 = *(const uint4*)base;
                k1 = *(const uint4*)(base + 8);
                v0 = *(const uint4*)(base + 32);
                v1 = *(const uint4*)(base + 40);
            }
            *(uint4*)(ksmz[z] + j * KSTRIDE)     = k0;
            *(uint4*)(ksmz[z] + j * KSTRIDE + 8) = k1;
            u32 vw[8] = {v0.x, v0.y, v0.z, v0.w, v1.x, v1.y, v1.z, v1.w};
#pragma unroll
            for (int i = 0; i < 8; i++) {
                __nv_bfloat162 pr = *(const __nv_bfloat162*)&vw[i];
                vsmz[z][(2 * i) * VSTRIDE + j]     = pr.x;
                vsmz[z][(2 * i + 1) * VSTRIDE + j] = pr.y;
            }
        }
    }

    u32 qa[2][2][4];
    int qwb = warp * 32;
#pragma unroll
    for (int z = 0; z < 2; z++) {
        const __nv_bfloat16* q = qbase + (size_t)z * HWP * 32;
#pragma unroll
        for (int m = 0; m < 2; m++) {
            int r0 = qwb + m * 16 + gid;
            int r1 = r0 + 8;
            int px0 = ((wy << 4) + (r0 >> 4)) * 256 + (wx << 4) + (r0 & 15);
            int px1 = ((wy << 4) + (r1 >> 4)) * 256 + (wx << 4) + (r1 & 15);
            const __nv_bfloat16* q0p = q + (size_t)px0 * 32 + (head << 4);
            const __nv_bfloat16* q1p = q + (size_t)px1 * 32 + (head << 4);
            qa[z][m][0] = *(const u32*)(q0p + 2 * tig);
            qa[z][m][1] = *(const u32*)(q1p + 2 * tig);
            qa[z][m][2] = *(const u32*)(q0p + 8 + 2 * tig);
            qa[z][m][3] = *(const u32*)(q1p + 8 + 2 * tig);
        }
    }
    __syncthreads();

    float o[2][2][2][4];
#pragma unroll
    for (int z = 0; z < 2; z++)
#pragma unroll
        for (int m = 0; m < 2; m++)
#pragma unroll
            for (int d = 0; d < 2; d++)
#pragma unroll
                for (int i = 0; i < 4; i++) o[z][m][d][i] = 0.f;
    float l4[2][4] = {{0.f, 0.f, 0.f, 0.f}, {0.f, 0.f, 0.f, 0.f}};

    const u64* bF = biasF + ((size_t)head << 8) * 144;

#pragma unroll 1
    for (int ch = 0; ch < 36; ch++) {
        int kb = ch * 16;
        u64 bw[4];
#pragma unroll
        for (int r4 = 0; r4 < 4; r4++) {
            int qrow = qwb + ((r4 >> 1) << 4) + ((r4 & 1) << 3) + gid;
            bw[r4] = bF[(qrow * 36 + ch) * 4 + tig];
        }
#pragma unroll
        for (int z = 0; z < 2; z++) {
            u32 kf[2][2];
#pragma unroll
            for (int nt = 0; nt < 2; nt++) {
                const __nv_bfloat16* kr = ksmz[z] + (kb + nt * 8 + gid) * KSTRIDE + 2 * tig;
                kf[nt][0] = *(const u32*)kr;
                kf[nt][1] = *(const u32*)(kr + 8);
            }
            u32 vb[2][2];
#pragma unroll
            for (int dt = 0; dt < 2; dt++) {
                const __nv_bfloat16* vr = vsmz[z] + (dt * 8 + gid) * VSTRIDE + kb + 2 * tig;
                vb[dt][0] = *(const u32*)vr;
                vb[dt][1] = *(const u32*)(vr + 8);
            }
#pragma unroll
            for (int m = 0; m < 2; m++) {
                float c0[4] = {0.f, 0.f, 0.f, 0.f}, c1[4] = {0.f, 0.f, 0.f, 0.f};
                mma_bf16(c0, qa[z][m], kf[0], c0);
                mma_bf16(c1, qa[z][m], kf[1], c1);
                u32 bAlo = (u32)bw[m * 2],     bAhi = (u32)(bw[m * 2] >> 32);
                u32 bBlo = (u32)bw[m * 2 + 1], bBhi = (u32)(bw[m * 2 + 1] >> 32);
                float p00 = ex2f(fminf(c0[0] + __int_as_float(bAlo << 16), 80.f));
                float p01 = ex2f(fminf(c0[1] + __int_as_float((int)(bAlo & 0xffff0000u)), 80.f));
                float p02 = ex2f(fminf(c0[2] + __int_as_float(bBlo << 16), 80.f));
                float p03 = ex2f(fminf(c0[3] + __int_as_float((int)(bBlo & 0xffff0000u)), 80.f));
                float p10 = ex2f(fminf(c1[0] + __int_as_float(bAhi << 16), 80.f));
                float p11 = ex2f(fminf(c1[1] + __int_as_float((int)(bAhi & 0xffff0000u)), 80.f));
                float p12 = ex2f(fminf(c1[2] + __int_as_float(bBhi << 16), 80.f));
                float p13 = ex2f(fminf(c1[3] + __int_as_float((int)(bBhi & 0xffff0000u)), 80.f));
                l4[z][m * 2]     += (p00 + p01) + (p10 + p11);
                l4[z][m * 2 + 1] += (p02 + p03) + (p12 + p13);
                u32 pa[4];
                pa[0] = bfpack(p00, p01);
                pa[1] = bfpack(p02, p03);
                pa[2] = bfpack(p10, p11);
                pa[3] = bfpack(p12, p13);
                mma_bf16(o[z][m][0], pa, vb[0], o[z][m][0]);
                mma_bf16(o[z][m][1], pa, vb[1], o[z][m][1]);
            }
        }
    }

#pragma unroll
    for (int z = 0; z < 2; z++)
#pragma unroll
        for (int r4 = 0; r4 < 4; r4++) {
            l4[z][r4] += __shfl_xor_sync(0xffffffffu, l4[z][r4], 1);
            l4[z][r4] += __shfl_xor_sync(0xffffffffu, l4[z][r4], 2);
            l4[z][r4] = 1.f / l4[z][r4];
        }

#pragma unroll
    for (int z = 0; z < 2; z++) {
        __nv_bfloat16* out = outbase + (size_t)z * HWP * 32;
#pragma unroll
        for (int m = 0; m < 2; m++) {
            int r0 = qwb + m * 16 + gid;
            int r1 = r0 + 8;
            int px0 = ((wy << 4) + (r0 >> 4)) * 256 + (wx << 4) + (r0 & 15);
            int px1 = ((wy << 4) + (r1 >> 4)) * 256 + (wx << 4) + (r1 & 15);
            __nv_bfloat16* o0p = out + (size_t)px0 * 32 + (head << 4);
            __nv_bfloat16* o1p = out + (size_t)px1 * 32 + (head << 4);
            float i0 = l4[z][m * 2], i1 = l4[z][m * 2 + 1];
#pragma unroll
            for (int dt = 0; dt < 2; dt++) {
                *(u32*)(o0p + dt * 8 + 2 * tig) =
                    bfpack(o[z][m][dt][0] * i0, o[z][m][dt][1] * i0);
                *(u32*)(o1p + dt * 8 + 2 * tig) =
                    bfpack(o[z][m][dt][2] * i1, o[z][m][dt][3] * i1);
            }
        }
    }
}

// ---------------- K8: OCAB tails, weight-amortized; + final sum + HWC->CHW ----------------
__global__ __launch_bounds__(256) void proj_mlp_kernel(
    const __nv_bfloat16* __restrict__ attbase,
    const float* __restrict__ xhwc, const float* __restrict__ t4,
    const float* __restrict__ x_chw,
    const float* __restrict__ stats,
    const float* __restrict__ in_g, const float* __restrict__ in_b,
    const float* __restrict__ wp, const float* __restrict__ bp,
    const float* __restrict__ n2g, const float* __restrict__ n2b,
    const float* __restrict__ mw1, const float* __restrict__ mb1,
    const float* __restrict__ mw2, const float* __restrict__ mb2,
    float* __restrict__ out) {
    __shared__ u64 s_wp2[512], s_m1a[512], s_m1b[512], s_m2[1024];
    __shared__ float s_bp[32], s_mb1[64], s_mb2[32], s_g[32], s_b[32], s_A[32], s_C[32];
    __shared__ __align__(16) float s_yn[8][PPW][32];     // 8 KB, act/yn tile
    __shared__ __align__(16) char  s_ovl[8][PPW * 64 * 4]; // 16 KB: h tile, then s_o overlay
    int tid = threadIdx.x;
    for (int idx = tid; idx < 512; idx += 256) {
        int i2 = idx >> 5, l = idx & 31;
        s_wp2[idx] = f2pack(wp[(2 * i2) * 32 + l], wp[(2 * i2 + 1) * 32 + l]);
        s_m1a[idx] = f2pack(mw1[(2 * i2) * 64 + l], mw1[(2 * i2 + 1) * 64 + l]);
        s_m1b[idx] = f2pack(mw1[(2 * i2) * 64 + 32 + l], mw1[(2 * i2 + 1) * 64 + 32 + l]);
    }
    for (int idx = tid; idx < 1024; idx += 256) {
        int i2 = idx >> 5, l = idx & 31;
        s_m2[idx] = f2pack(mw2[(2 * i2) * 32 + l], mw2[(2 * i2 + 1) * 32 + l]);
    }
    if (tid < 32) {
        s_bp[tid] = bp[tid]; s_mb2[tid] = mb2[tid]; s_g[tid] = n2g[tid]; s_b[tid] = n2b[tid];
        float A = stats[32 + tid] * in_g[tid];
        s_A[tid] = A;
        s_C[tid] = in_b[tid] - stats[tid] * A;
    }
    if (tid < 64) s_mb1[tid] = mb1[tid];
    __syncthreads();
    int lane = tid & 31, w = tid >> 5;
    int p0blk = blockIdx.x * 64;
    int pbase = p0blk + w * PPW;
    float* s_h = (float*)&s_ovl[w][0];   // per-warp [PPW][64]

    float sc8[2][PPW];
#pragma unroll
    for (int it = 0; it < PPW; it++) {
        int p = pbase + it;
        sc8[0][it] = xhwc[p * 32 + lane];
        sc8[1][it] = t4[p * 32 + lane] * s_A[lane] + s_C[lane];
    }

    float osum[PPW];
#pragma unroll
    for (int it = 0; it < PPW; it++) osum[it] = 0.f;

#pragma unroll 1
    for (int z = 0; z < 2; z++) {
        // load att acts for all pixels
#pragma unroll
        for (int it = 0; it < PPW; it++)
            s_yn[w][it][lane] =
                __bfloat162float(attbase[(size_t)z * HWP * 32 + (pbase + it) * 32 + lane]);
        __syncwarp();
        // out-proj amortized
        float y[PPW];
        {
            u64 aq[PPW];
#pragma unroll
            for (int it = 0; it < PPW; it++) aq[it] = 0ULL;
#pragma unroll
            for (int i2 = 0; i2 < 16; i2++) {
                u64 wv = s_wp2[i2 * 32 + lane];
#pragma unroll
                for (int it = 0; it < PPW; it++) {
                    u64 x2 = *(const u64*)&s_yn[w][it][2 * i2];
                    aq[it] = f2fma(x2, wv, aq[it]);
                }
            }
#pragma unroll
            for (int it = 0; it < PPW; it++) {
                float2 fy = f2unpack(aq[it]);
                y[it] = fy.x + fy.y + s_bp[lane] + sc8[z][it];
            }
        }
        __syncwarp();
        // LN per pixel -> yn tile
#pragma unroll 1
        for (int it = 0; it < PPW; it++) {
            float mean = warp_sum(y[it]) * (1.f / 32.f);
            float dv = y[it] - mean;
            float var = warp_sum(dv * dv) * (1.f / 32.f);
            s_yn[w][it][lane] = dv * rsqrtf(var + 1e-5f) * s_g[lane] + s_b[lane];
        }
        __syncwarp();
        // MLP1 amortized: chain h0 then h1 (register economy)
        {
            u64 ha[PPW];
#pragma unroll
            for (int it = 0; it < PPW; it++) ha[it] = 0ULL;
#pragma unroll
            for (int i2 = 0; i2 < 16; i2++) {
                u64 wv = s_m1a[i2 * 32 + lane];
#pragma unroll
                for (int it = 0; it < PPW; it++) {
                    u64 x2 = *(const u64*)&s_yn[w][it][2 * i2];
                    ha[it] = f2fma(x2, wv, ha[it]);
                }
            }
#pragma unroll
            for (int it = 0; it < PPW; it++) {
                float2 f0 = f2unpack(ha[it]);
                s_h[it * 64 + lane] = gelu_tanh(f0.x + f0.y + s_mb1[lane]);
            }
#pragma unroll
            for (int it = 0; it < PPW; it++) ha[it] = 0ULL;
#pragma unroll
            for (int i2 = 0; i2 < 16; i2++) {
                u64 wv = s_m1b[i2 * 32 + lane];
#pragma unroll
                for (int it = 0; it < PPW; it++) {
                    u64 x2 = *(const u64*)&s_yn[w][it][2 * i2];
                    ha[it] = f2fma(x2, wv, ha[it]);
                }
            }
#pragma unroll
            for (int it = 0; it < PPW; it++) {
                float2 f1 = f2unpack(ha[it]);
                s_h[it * 64 + 32 + lane] = gelu_tanh(f1.x + f1.y + s_mb1[lane + 32]);
            }
        }
        __syncwarp();
        // MLP2 amortized
        {
            u64 r2[PPW];
#pragma unroll
            for (int it = 0; it < PPW; it++) r2[it] = 0ULL;
#pragma unroll
            for (int i2 = 0; i2 < 32; i2++) {
                u64 wv = s_m2[i2 * 32 + lane];
#pragma unroll
                for (int it = 0; it < PPW; it++) {
                    u64 g2 = *(const u64*)&s_h[it * 64 + 2 * i2];
                    r2[it] = f2fma(g2, wv, r2[it]);
                }
            }
#pragma unroll
            for (int it = 0; it < PPW; it++) {
                float2 fr = f2unpack(r2[it]);
                osum[it] += y[it] + fr.x + fr.y + s_mb2[lane];
            }
        }
        __syncwarp();
    }

    // epilogue: overlay s_ovl as block-wide [64][33] transpose tile
    __syncthreads();
    float (*s_o)[33] = (float(*)[33])&s_ovl[0][0];
#pragma unroll
    for (int it = 0; it < PPW; it++) s_o[w * PPW + it][lane] = osum[it];
    __syncthreads();
#pragma unroll
    for (int e = tid; e < 2048; e += 256) {
        int c = e >> 6, px = e & 63;
        int gp = p0blk + px;
        out[c * HWP + gp] = s_o[px][c] + x_chw[c * HWP + gp];
    }
}

// ---------------- launch ----------------
extern "C" void kernel_launch(void* const* d_in, const int* in_sizes, int n_in,
                              void* d_out, int out_size) {
    const float* x    = (const float*)d_in[0];
    const float* dep  = (const float*)d_in[1];
    const int*   rpi  = (const int*)  d_in[2];
    const float* cw1  = (const float*)d_in[3];
    const float* cb1  = (const float*)d_in[4];
    const float* cw2  = (const float*)d_in[5];
    const float* cb2  = (const float*)d_in[6];
    const float* cw3  = (const float*)d_in[7];
    const float* cb3  = (const float*)d_in[8];
    const float* cw4  = (const float*)d_in[9];
    const float* cb4  = (const float*)d_in[10];
    const float* in_g = (const float*)d_in[11];
    const float* in_b = (const float*)d_in[12];
    const float* n1g  = (const float*)d_in[13];
    const float* n1b  = (const float*)d_in[14];
    const float* wq   = (const float*)d_in[15];
    const float* bq   = (const float*)d_in[16];
    const float* wkv  = (const float*)d_in[17];
    const float* bkv  = (const float*)d_in[18];
    const float* rpb  = (const float*)d_in[19];
    const float* wp   = (const float*)d_in[20];
    const float* bp   = (const float*)d_in[21];
    const float* n2g  = (const float*)d_in[22];
    const float* n2b  = (const float*)d_in[23];
    const float* mw1  = (const float*)d_in[24];
    const float* mb1  = (const float*)d_in[25];
    const float* mw2  = (const float*)d_in[26];
    const float* mb2  = (const float*)d_in[27];
    float* out = (float*)d_out;

    void *p_xhwc, *p_t4, *p_q, *p_kv, *p_att, *p_bias, *p_stats, *p_part;
    cudaGetSymbolAddress(&p_xhwc, g_xhwc);
    cudaGetSymbolAddress(&p_t4, g_t4);
    cudaGetSymbolAddress(&p_q, g_qbf);
    cudaGetSymbolAddress(&p_kv, g_kvbf);
    cudaGetSymbolAddress(&p_att, g_attbf);
    cudaGetSymbolAddress(&p_bias, g_biasF);
    cudaGetSymbolAddress(&p_stats, g_stats);
    cudaGetSymbolAddress(&p_part, g_part);

    cudaFuncSetAttribute(attn_kernel, cudaFuncAttributeMaxDynamicSharedMemorySize, SMEM_ATTN);

    chw2hwc_kernel<<<2048, dim3(32, 8)>>>(x, (float*)p_xhwc);
    stem_fused_kernel<<<256, 256>>>(dep, cw1, cb1, cw2, cb2, cw3, cb3, cw4, cb4,
                                    (float*)p_t4);
    inorm_part_kernel<<<512, 256>>>((float*)p_t4, (float*)p_part);
    inorm_final_kernel<<<1, 1024>>>((float*)p_part, (float*)p_stats);
    build_biasF_kernel<<<288, 256>>>(rpi, rpb, (u64*)p_bias);

    ln_qkv_kernel<<<HWP / (8 * PPW), 256>>>(
        (float*)p_xhwc, (float*)p_t4, (float*)p_stats, in_g, in_b, n1g, n1b,
        wq, bq, wkv, bkv, (__nv_bfloat16*)p_q, (__nv_bfloat16*)p_kv);
    attn_kernel<<<dim3(NWIN, 2), 256, SMEM_ATTN>>>((__nv_bfloat16*)p_q,
                                                   (__nv_bfloat16*)p_kv,
                                                   (u64*)p_bias,
                                                   (__nv_bfloat16*)p_att);
    proj_mlp_kernel<<<HWP / 64, 256>>>(
        (__nv_bfloat16*)p_att, (float*)p_xhwc, (float*)p_t4, x, (float*)p_stats,
        in_g, in_b, wp, bp, n2g, n2b, mw1, mb1, mw2, mb2, out);
}

// round 15
// speedup vs baseline: 1.3128x; 1.1023x over previous
#include <cuda_runtime.h>
#include <cuda_bf16.h>
#include <math.h>

// Problem constants: B=1, C=32, H=W=256, WS=16, OWS=24, NH=2, d=16
#define HWP   65536
#define NKEY  576
#define NQ    256
#define NWIN  256

typedef unsigned long long u64;
typedef unsigned int u32;

#define LOG2E 1.4426950408889634f

// attn smem layout (both z resident)
#define KSTRIDE 24
#define VSTRIDE 584
#define KBYTES (NKEY * KSTRIDE * 2)          // 27648
#define VBYTES (16 * VSTRIDE * 2)            // 18688
#define SMEM_ATTN (2 * KBYTES + 2 * VBYTES)  // 92672

#define PPW 8

// ---------------- scratch ----------------
__device__ float          g_xhwc [HWP * 32];
__device__ float          g_t4   [HWP * 32];
__device__ __nv_bfloat16  g_qbf  [2 * HWP * 32];
__device__ __nv_bfloat16  g_kvbf [2 * HWP * 64];
__device__ __nv_bfloat16  g_attbf[2 * HWP * 32];
__device__ u64            g_biasF[2 * NQ * 36 * 4];
__device__ float          g_stats[64];
__device__ float          g_part [512 * 64];

// ---------------- helpers ----------------
__device__ __forceinline__ u64 f2pack(float lo, float hi) {
    u64 r; asm("mov.b64 %0, {%1, %2};" : "=l"(r) : "f"(lo), "f"(hi)); return r;
}
__device__ __forceinline__ float2 f2unpack(u64 v) {
    float2 f; asm("mov.b64 {%0, %1}, %2;" : "=f"(f.x), "=f"(f.y) : "l"(v)); return f;
}
__device__ __forceinline__ u64 f2fma(u64 a, u64 b, u64 c) {
    u64 d; asm("fma.rn.f32x2 %0, %1, %2, %3;" : "=l"(d) : "l"(a), "l"(b), "l"(c)); return d;
}
__device__ __forceinline__ float ex2f(float x) {
    float y; asm("ex2.approx.f32 %0, %1;" : "=f"(y) : "f"(x)); return y;
}
__device__ __forceinline__ u32 bfpack(float lo, float hi) {
    u32 d; asm("cvt.rn.bf16x2.f32 %0, %1, %2;" : "=r"(d) : "f"(hi), "f"(lo)); return d;
}
__device__ __forceinline__ u32 badd2(u32 a, u32 b) {
    u32 d; asm("add.rn.bf16x2 %0, %1, %2;" : "=r"(d) : "r"(a), "r"(b)); return d;
}
__device__ __forceinline__ u32 bmin2(u32 a, u32 b) {
    u32 d; asm("min.bf16x2 %0, %1, %2;" : "=r"(d) : "r"(a), "r"(b)); return d;
}
__device__ __forceinline__ u32 bex2(u32 a) {
    u32 d; asm("ex2.approx.ftz.bf16x2 %0, %1;" : "=r"(d) : "r"(a)); return d;
}
__device__ __forceinline__ float bpair_sum(u32 p) {
    __nv_bfloat162 h = *(__nv_bfloat162*)&p;
    return __low2float(h) + __high2float(h);
}
__device__ __forceinline__ float warp_sum(float v) {
#pragma unroll
    for (int o = 16; o; o >>= 1) v += __shfl_xor_sync(0xffffffffu, v, o);
    return v;
}
__device__ __forceinline__ float gelu_tanh(float x) {
    float z = 0.7978845608028654f * (x + 0.044715f * x * x * x);
    float e = ex2f(2.8853900817779268f * z);
    float t = 1.f - __fdividef(2.f, e + 1.f);
    return 0.5f * x * (1.f + t);
}
__device__ __forceinline__ void mma_bf16(float* d, const u32* a, const u32* b, const float* c) {
    asm("mma.sync.aligned.m16n8k16.row.col.f32.bf16.bf16.f32 "
        "{%0,%1,%2,%3}, {%4,%5,%6,%7}, {%8,%9}, {%10,%11,%12,%13};"
        : "=f"(d[0]), "=f"(d[1]), "=f"(d[2]), "=f"(d[3])
        : "r"(a[0]), "r"(a[1]), "r"(a[2]), "r"(a[3]),
          "r"(b[0]), "r"(b[1]),
          "f"(c[0]), "f"(c[1]), "f"(c[2]), "f"(c[3]));
}

// ---------------- K0: CHW -> HWC transpose of x ----------------
__global__ void chw2hwc_kernel(const float* __restrict__ x, float* __restrict__ xh) {
    __shared__ float sm[32][33];
    int p0 = blockIdx.x * 32;
    int tx = threadIdx.x, ty = threadIdx.y;
    for (int c = ty; c < 32; c += 8) sm[c][tx] = x[c * HWP + p0 + tx];
    __syncthreads();
    for (int r = ty; r < 32; r += 8) xh[(p0 + r) * 32 + tx] = sm[tx][r];
}

// ---------------- K1: fused stem ----------------
__global__ __launch_bounds__(256) void stem_fused_kernel(
    const float* __restrict__ depth,
    const float* __restrict__ cw1, const float* __restrict__ cb1,
    const float* __restrict__ cw2, const float* __restrict__ cb2,
    const float* __restrict__ cw3, const float* __restrict__ cb3,
    const float* __restrict__ cw4, const float* __restrict__ cb4,
    float* __restrict__ t4) {
    __shared__ float w1[72], b1s[8], w2[128], b2s[16];
    __shared__ u64 w3p[1152];
    __shared__ u64 w4p[256];
    __shared__ float b3[16], b4[32];
    __shared__ float t2s[324][17];
    int tid = threadIdx.x;
    if (tid < 72)  w1[tid]  = cw1[tid];
    if (tid < 8)   b1s[tid] = cb1[tid];
    if (tid < 128) w2[tid]  = cw2[tid];
    if (tid < 16)  b2s[tid] = cb2[tid];
    for (int i = tid; i < 1152; i += 256) {
        int oc = i / 72, r = i - oc * 72, tap = r >> 3, ic2 = r & 7;
        w3p[i] = f2pack(cw3[oc * 144 + (2 * ic2) * 9 + tap],
                        cw3[oc * 144 + (2 * ic2 + 1) * 9 + tap]);
    }
    if (tid < 256) {
        int c4 = tid >> 3, o2 = tid & 7;
        w4p[tid] = f2pack(cw4[c4 * 16 + 2 * o2], cw4[c4 * 16 + 2 * o2 + 1]);
    }
    if (tid < 16) b3[tid] = cb3[tid];
    if (tid < 32) b4[tid] = cb4[tid];
    __syncthreads();

    int ty0 = (blockIdx.x >> 4) << 4;
    int tx0 = (blockIdx.x & 15) << 4;

    for (int h = tid; h < 324; h += 256) {
        int hy = h / 18, hx = h - hy * 18;
        int gy = ty0 + hy - 1, gx = tx0 + hx - 1;
        float out16[16];
        if ((unsigned)gy < 256u && (unsigned)gx < 256u) {
            float d[9];
#pragma unroll
            for (int tap = 0; tap < 9; tap++) {
                int yy = gy + tap / 3 - 1, xx = gx + tap % 3 - 1;
                d[tap] = ((unsigned)yy < 256u && (unsigned)xx < 256u)
                             ? depth[(yy << 8) + xx] : 0.f;
            }
            float c1[8];
#pragma unroll
            for (int o = 0; o < 8; o++) {
                float a = b1s[o];
#pragma unroll
                for (int tap = 0; tap < 9; tap++) a += d[tap] * w1[o * 9 + tap];
                c1[o] = fmaxf(a, 0.f);
            }
#pragma unroll
            for (int o2 = 0; o2 < 16; o2++) {
                float a = b2s[o2];
#pragma unroll
                for (int o = 0; o < 8; o++) a += c1[o] * w2[o2 * 8 + o];
                out16[o2] = fmaxf(a, 0.f);
            }
        } else {
#pragma unroll
            for (int o2 = 0; o2 < 16; o2++) out16[o2] = 0.f;
        }
#pragma unroll
        for (int o2 = 0; o2 < 16; o2++) t2s[h][o2] = out16[o2];
    }
    __syncthreads();

    int py = tid >> 4, px = tid & 15;
    u64 acc2[16];
#pragma unroll
    for (int i = 0; i < 16; i++) acc2[i] = 0ULL;
#pragma unroll 1
    for (int tap = 0; tap < 9; tap++) {
        int hh = (py + tap / 3) * 18 + (px + tap % 3);
        const float* src = &t2s[hh][0];
        u64 in2[8];
#pragma unroll
        for (int k = 0; k < 8; k++) in2[k] = f2pack(src[2 * k], src[2 * k + 1]);
        const u64* wt = &w3p[tap * 8];
#pragma unroll
        for (int oc = 0; oc < 16; oc++) {
            const u64* wr = wt + oc * 72;
#pragma unroll
            for (int k = 0; k < 8; k++) acc2[oc] = f2fma(in2[k], wr[k], acc2[oc]);
        }
    }
    float c3[16];
#pragma unroll
    for (int oc = 0; oc < 16; oc++) {
        float2 f = f2unpack(acc2[oc]);
        c3[oc] = fmaxf(f.x + f.y + b3[oc], 0.f);
    }
    u64 a2[8];
#pragma unroll
    for (int o2 = 0; o2 < 8; o2++) a2[o2] = f2pack(c3[2 * o2], c3[2 * o2 + 1]);
    int p = (ty0 + py) * 256 + tx0 + px;
    float* dst = t4 + (size_t)p * 32;
#pragma unroll
    for (int c4 = 0; c4 < 32; c4++) {
        u64 r = 0ULL;
#pragma unroll
        for (int o2 = 0; o2 < 8; o2++) r = f2fma(a2[o2], w4p[c4 * 8 + o2], r);
        float2 f = f2unpack(r);
        dst[c4] = f.x + f.y + b4[c4];
    }
}

// ---------------- K3a: instance-norm partial sums ----------------
__global__ __launch_bounds__(256) void inorm_part_kernel(const float* __restrict__ t4,
                                                         float* __restrict__ part) {
    int tid = threadIdx.x;
    size_t base = (size_t)blockIdx.x * 4096;
    float s[4] = {0, 0, 0, 0}, s2[4] = {0, 0, 0, 0};
    const float4* src = (const float4*)(t4 + base);
#pragma unroll
    for (int it = 0; it < 4; it++) {
        float4 v = src[it * 256 + tid];
        s[0] += v.x; s2[0] += v.x * v.x;
        s[1] += v.y; s2[1] += v.y * v.y;
        s[2] += v.z; s2[2] += v.z * v.z;
        s[3] += v.w; s2[3] += v.w * v.w;
    }
    __shared__ float sa[256][4], sb[256][4];
#pragma unroll
    for (int k = 0; k < 4; k++) { sa[tid][k] = s[k]; sb[tid][k] = s2[k]; }
    __syncthreads();
    if (tid < 32) {
        int grp = tid >> 2, k = tid & 3;
        float a = 0.f, b = 0.f;
#pragma unroll
        for (int t8 = 0; t8 < 32; t8++) {
            a += sa[t8 * 8 + grp][k];
            b += sb[t8 * 8 + grp][k];
        }
        part[blockIdx.x * 64 + tid] = a;
        part[blockIdx.x * 64 + 32 + tid] = b;
    }
}

// ---------------- K3b: instance-norm final reduce ----------------
__global__ __launch_bounds__(1024) void inorm_final_kernel(const float* __restrict__ part,
                                                           float* __restrict__ stats) {
    int tid = threadIdx.x;
    int c = tid & 31, g = tid >> 5;
    double a = 0.0, b = 0.0;
#pragma unroll
    for (int i = 0; i < 16; i++) {
        int blk = g * 16 + i;
        a += (double)part[blk * 64 + c];
        b += (double)part[blk * 64 + 32 + c];
    }
    __shared__ double sa[32][33], sb[32][33];
    sa[g][c] = a; sb[g][c] = b;
    __syncthreads();
    for (int o = 16; o; o >>= 1) {
        if (g < o) {
            sa[g][c] += sa[g + o][c];
            sb[g][c] += sb[g + o][c];
        }
        __syncthreads();
    }
    if (tid < 32) {
        double mean = sa[0][tid] / (double)HWP;
        double var = sb[0][tid] / (double)HWP - mean * mean;
        stats[tid] = (float)mean;
        stats[32 + tid] = rsqrtf((float)var + 1e-5f);
    }
}

// ---------------- K5: bias fragments ----------------
__global__ void build_biasF_kernel(const int* __restrict__ rpi, const float* __restrict__ rpb,
                                   u64* __restrict__ biasF) {
    int idx = blockIdx.x * 256 + threadIdx.x;
    int tig = idx & 3;
    int t2 = idx >> 2;
    int ch = t2 % 36;
    int t3 = t2 / 36;
    int q = t3 & 255;
    int h = t3 >> 8;
    int k0 = ch * 16 + 2 * tig;
    u64 r = 0;
#pragma unroll
    for (int e = 0; e < 4; e++) {
        int k = k0 + (e >> 1) * 8 + (e & 1);
        float v = rpb[rpi[q * NKEY + k] * 2 + h] * LOG2E;
        unsigned short us = __bfloat16_as_ushort(__float2bfloat16(v));
        r |= (u64)us << (16 * e);
    }
    biasF[idx] = r;
}

// ---------------- K6: LN once; weight-amortized projections ----------------
__global__ __launch_bounds__(256) void ln_qkv_kernel(
    const float* __restrict__ xhwc, const float* __restrict__ t4,
    const float* __restrict__ stats,
    const float* __restrict__ in_g, const float* __restrict__ in_b,
    const float* __restrict__ n1g, const float* __restrict__ n1b,
    const float* __restrict__ wq, const float* __restrict__ bq,
    const float* __restrict__ wkv, const float* __restrict__ bkv,
    __nv_bfloat16* __restrict__ qbase, __nv_bfloat16* __restrict__ kvbase) {
    __shared__ u64 s_wq2[512], s_wk2[512], s_wv2[512];
    __shared__ float s_bq[32], s_bkv[64], s_g[32], s_b[32], s_A[32], s_C[32];
    __shared__ __align__(16) float s_actx[8][PPW][32];
    __shared__ __align__(16) float s_actf[8][PPW][32];
    int tid = threadIdx.x;
    for (int idx = tid; idx < 512; idx += 256) {
        int i2 = idx >> 5, l = idx & 31;
        s_wq2[idx] = f2pack(wq[(2 * i2) * 32 + l], wq[(2 * i2 + 1) * 32 + l]);
        s_wk2[idx] = f2pack(wkv[(2 * i2) * 64 + l], wkv[(2 * i2 + 1) * 64 + l]);
        s_wv2[idx] = f2pack(wkv[(2 * i2) * 64 + 32 + l], wkv[(2 * i2 + 1) * 64 + 32 + l]);
    }
    if (tid < 32) {
        s_bq[tid] = bq[tid]; s_g[tid] = n1g[tid]; s_b[tid] = n1b[tid];
        float A = stats[32 + tid] * in_g[tid];
        s_A[tid] = A;
        s_C[tid] = in_b[tid] - stats[tid] * A;
    }
    if (tid < 64) s_bkv[tid] = bkv[tid];
    __syncthreads();
    __nv_bfloat16* q0  = qbase;
    __nv_bfloat16* q1  = qbase + (size_t)HWP * 32;
    __nv_bfloat16* kv0 = kvbase;
    __nv_bfloat16* kv1 = kvbase + (size_t)HWP * 64;
    int lane = tid & 31, w = tid >> 5;
    int pbase = blockIdx.x * (8 * PPW) + w * PPW;
    const float QS = 0.25f * LOG2E;

#pragma unroll 1
    for (int it = 0; it < PPW; it++) {
        int p = pbase + it;
        float xv = xhwc[p * 32 + lane];
        float fvv = t4[p * 32 + lane] * s_A[lane] + s_C[lane];
        float mx = warp_sum(xv) * (1.f / 32.f);
        float dx = xv - mx;
        float vx = warp_sum(dx * dx) * (1.f / 32.f);
        s_actx[w][it][lane] = dx * rsqrtf(vx + 1e-5f) * s_g[lane] + s_b[lane];
        float mf = warp_sum(fvv) * (1.f / 32.f);
        float df = fvv - mf;
        float vf = warp_sum(df * df) * (1.f / 32.f);
        s_actf[w][it][lane] = df * rsqrtf(vf + 1e-5f) * s_g[lane] + s_b[lane];
    }
    __syncwarp();

#pragma unroll 1
    for (int side = 0; side < 2; side++) {
        const float* act = side ? &s_actf[w][0][0] : &s_actx[w][0][0];
        __nv_bfloat16* qo  = side ? q1 : q0;
        __nv_bfloat16* kvo = side ? kv0 : kv1;
        u64 aq[PPW], ak[PPW], av[PPW];
#pragma unroll
        for (int it = 0; it < PPW; it++) { aq[it] = 0ULL; ak[it] = 0ULL; av[it] = 0ULL; }
#pragma unroll
        for (int i2 = 0; i2 < 16; i2++) {
            u64 wqv = s_wq2[i2 * 32 + lane];
            u64 wkw = s_wk2[i2 * 32 + lane];
            u64 wvw = s_wv2[i2 * 32 + lane];
#pragma unroll
            for (int it = 0; it < PPW; it++) {
                u64 x2 = *(const u64*)&act[it * 32 + 2 * i2];
                aq[it] = f2fma(x2, wqv, aq[it]);
                ak[it] = f2fma(x2, wkw, ak[it]);
                av[it] = f2fma(x2, wvw, av[it]);
            }
        }
#pragma unroll
        for (int it = 0; it < PPW; it++) {
            int p = pbase + it;
            float2 fq = f2unpack(aq[it]), fk = f2unpack(ak[it]), fv2 = f2unpack(av[it]);
            qo[p * 32 + lane] = __float2bfloat16((fq.x + fq.y + s_bq[lane]) * QS);
            kvo[p * 64 + lane]      = __float2bfloat16(fk.x + fk.y + s_bkv[lane]);
            kvo[p * 64 + 32 + lane] = __float2bfloat16(fv2.x + fv2.y + s_bkv[lane + 32]);
        }
    }
}

// ---------------- K7: flash attention, bf16x2 exp path ----------------
__global__ __launch_bounds__(256) void attn_kernel(
    const __nv_bfloat16* __restrict__ qbase, const __nv_bfloat16* __restrict__ kvbase,
    const u64* __restrict__ biasF, __nv_bfloat16* __restrict__ outbase) {
    extern __shared__ __align__(16) char smraw[];
    int win = blockIdx.x, head = blockIdx.y;
    int wy = win >> 4, wx = win & 15;
    int t = threadIdx.x;
    int warp = t >> 5, lane = t & 31;
    int gid = lane >> 2, tig = lane & 3;
    const u32 P80 = 0x42A042A0u;   // bf16(80) packed x2

    __nv_bfloat16* ksmz[2] = {(__nv_bfloat16*)smraw, (__nv_bfloat16*)(smraw + KBYTES)};
    __nv_bfloat16* vsmz[2] = {(__nv_bfloat16*)(smraw + 2 * KBYTES),
                              (__nv_bfloat16*)(smraw + 2 * KBYTES + VBYTES)};

    for (int j = t; j < NKEY; j += 256) {
        int jy = j / 24, jx = j - jy * 24;
        int yy = (wy << 4) - 4 + jy, xx = (wx << 4) - 4 + jx;
        bool inb = ((unsigned)yy < 256u && (unsigned)xx < 256u);
#pragma unroll
        for (int z = 0; z < 2; z++) {
            uint4 k0 = make_uint4(0, 0, 0, 0), k1 = k0, v0 = k0, v1 = k0;
            if (inb) {
                const __nv_bfloat16* base = kvbase + (size_t)z * HWP * 64 +
                                            ((size_t)((yy << 8) + xx) << 6) + (head << 4);
                k0 = *(const uint4*)base;
                k1 = *(const uint4*)(base + 8);
                v0 = *(const uint4*)(base + 32);
                v1 = *(const uint4*)(base + 40);
            }
            *(uint4*)(ksmz[z] + j * KSTRIDE)     = k0;
            *(uint4*)(ksmz[z] + j * KSTRIDE + 8) = k1;
            u32 vw[8] = {v0.x, v0.y, v0.z, v0.w, v1.x, v1.y, v1.z, v1.w};
#pragma unroll
            for (int i = 0; i < 8; i++) {
                __nv_bfloat162 pr = *(const __nv_bfloat162*)&vw[i];
                vsmz[z][(2 * i) * VSTRIDE + j]     = pr.x;
                vsmz[z][(2 * i + 1) * VSTRIDE + j] = pr.y;
            }
        }
    }

    u32 qa[2][2][4];
    int qwb = warp * 32;
#pragma unroll
    for (int z = 0; z < 2; z++) {
        const __nv_bfloat16* q = qbase + (size_t)z * HWP * 32;
#pragma unroll
        for (int m = 0; m < 2; m++) {
            int r0 = qwb + m * 16 + gid;
            int r1 = r0 + 8;
            int px0 = ((wy << 4) + (r0 >> 4)) * 256 + (wx << 4) + (r0 & 15);
            int px1 = ((wy << 4) + (r1 >> 4)) * 256 + (wx << 4) + (r1 & 15);
            const __nv_bfloat16* q0p = q + (size_t)px0 * 32 + (head << 4);
            const __nv_bfloat16* q1p = q + (size_t)px1 * 32 + (head << 4);
            qa[z][m][0] = *(const u32*)(q0p + 2 * tig);
            qa[z][m][1] = *(const u32*)(q1p + 2 * tig);
            qa[z][m][2] = *(const u32*)(q0p + 8 + 2 * tig);
            qa[z][m][3] = *(const u32*)(q1p + 8 + 2 * tig);
        }
    }
    __syncthreads();

    float o[2][2][2][4];
#pragma unroll
    for (int z = 0; z < 2; z++)
#pragma unroll
        for (int m = 0; m < 2; m++)
#pragma unroll
            for (int d = 0; d < 2; d++)
#pragma unroll
                for (int i = 0; i < 4; i++) o[z][m][d][i] = 0.f;
    float l4[2][4] = {{0.f, 0.f, 0.f, 0.f}, {0.f, 0.f, 0.f, 0.f}};

    const u64* bF = biasF + ((size_t)head << 8) * 144;

#pragma unroll 1
    for (int ch = 0; ch < 36; ch++) {
        int kb = ch * 16;
        u64 bw[4];
#pragma unroll
        for (int r4 = 0; r4 < 4; r4++) {
            int qrow = qwb + ((r4 >> 1) << 4) + ((r4 & 1) << 3) + gid;
            bw[r4] = bF[(qrow * 36 + ch) * 4 + tig];
        }
#pragma unroll
        for (int z = 0; z < 2; z++) {
            u32 kf[2][2];
#pragma unroll
            for (int nt = 0; nt < 2; nt++) {
                const __nv_bfloat16* kr = ksmz[z] + (kb + nt * 8 + gid) * KSTRIDE + 2 * tig;
                kf[nt][0] = *(const u32*)kr;
                kf[nt][1] = *(const u32*)(kr + 8);
            }
            u32 vb[2][2];
#pragma unroll
            for (int dt = 0; dt < 2; dt++) {
                const __nv_bfloat16* vr = vsmz[z] + (dt * 8 + gid) * VSTRIDE + kb + 2 * tig;
                vb[dt][0] = *(const u32*)vr;
                vb[dt][1] = *(const u32*)(vr + 8);
            }
#pragma unroll
            for (int m = 0; m < 2; m++) {
                float c0[4] = {0.f, 0.f, 0.f, 0.f}, c1[4] = {0.f, 0.f, 0.f, 0.f};
                mma_bf16(c0, qa[z][m], kf[0], c0);
                mma_bf16(c1, qa[z][m], kf[1], c1);
                u32 bAlo = (u32)bw[m * 2],     bAhi = (u32)(bw[m * 2] >> 32);
                u32 bBlo = (u32)bw[m * 2 + 1], bBhi = (u32)(bw[m * 2 + 1] >> 32);
                u32 pa[4];
                pa[0] = bex2(bmin2(badd2(bfpack(c0[0], c0[1]), bAlo), P80));
                pa[1] = bex2(bmin2(badd2(bfpack(c0[2], c0[3]), bBlo), P80));
                pa[2] = bex2(bmin2(badd2(bfpack(c1[0], c1[1]), bAhi), P80));
                pa[3] = bex2(bmin2(badd2(bfpack(c1[2], c1[3]), bBhi), P80));
                l4[z][m * 2]     += bpair_sum(pa[0]) + bpair_sum(pa[2]);
                l4[z][m * 2 + 1] += bpair_sum(pa[1]) + bpair_sum(pa[3]);
                mma_bf16(o[z][m][0], pa, vb[0], o[z][m][0]);
                mma_bf16(o[z][m][1], pa, vb[1], o[z][m][1]);
            }
        }
    }

#pragma unroll
    for (int z = 0; z < 2; z++)
#pragma unroll
        for (int r4 = 0; r4 < 4; r4++) {
            l4[z][r4] += __shfl_xor_sync(0xffffffffu, l4[z][r4], 1);
            l4[z][r4] += __shfl_xor_sync(0xffffffffu, l4[z][r4], 2);
            l4[z][r4] = 1.f / l4[z][r4];
        }

#pragma unroll
    for (int z = 0; z < 2; z++) {
        __nv_bfloat16* out = outbase + (size_t)z * HWP * 32;
#pragma unroll
        for (int m = 0; m < 2; m++) {
            int r0 = qwb + m * 16 + gid;
            int r1 = r0 + 8;
            int px0 = ((wy << 4) + (r0 >> 4)) * 256 + (wx << 4) + (r0 & 15);
            int px1 = ((wy << 4) + (r1 >> 4)) * 256 + (wx << 4) + (r1 & 15);
            __nv_bfloat16* o0p = out + (size_t)px0 * 32 + (head << 4);
            __nv_bfloat16* o1p = out + (size_t)px1 * 32 + (head << 4);
            float i0 = l4[z][m * 2], i1 = l4[z][m * 2 + 1];
#pragma unroll
            for (int dt = 0; dt < 2; dt++) {
                *(u32*)(o0p + dt * 8 + 2 * tig) =
                    bfpack(o[z][m][dt][0] * i0, o[z][m][dt][1] * i0);
                *(u32*)(o1p + dt * 8 + 2 * tig) =
                    bfpack(o[z][m][dt][2] * i1, o[z][m][dt][3] * i1);
            }
        }
    }
}

// ---------------- K8: OCAB tails, weight-amortized; + final sum + HWC->CHW ----------------
__global__ __launch_bounds__(256) void proj_mlp_kernel(
    const __nv_bfloat16* __restrict__ attbase,
    const float* __restrict__ xhwc, const float* __restrict__ t4,
    const float* __restrict__ x_chw,
    const float* __restrict__ stats,
    const float* __restrict__ in_g, const float* __restrict__ in_b,
    const float* __restrict__ wp, const float* __restrict__ bp,
    const float* __restrict__ n2g, const float* __restrict__ n2b,
    const float* __restrict__ mw1, const float* __restrict__ mb1,
    const float* __restrict__ mw2, const float* __restrict__ mb2,
    float* __restrict__ out) {
    __shared__ u64 s_wp2[512], s_m1a[512], s_m1b[512], s_m2[1024];
    __shared__ float s_bp[32], s_mb1[64], s_mb2[32], s_g[32], s_b[32], s_A[32], s_C[32];
    __shared__ __align__(16) float s_yn[8][PPW][32];
    __shared__ __align__(16) char  s_ovl[8][PPW * 64 * 4];
    int tid = threadIdx.x;
    for (int idx = tid; idx < 512; idx += 256) {
        int i2 = idx >> 5, l = idx & 31;
        s_wp2[idx] = f2pack(wp[(2 * i2) * 32 + l], wp[(2 * i2 + 1) * 32 + l]);
        s_m1a[idx] = f2pack(mw1[(2 * i2) * 64 + l], mw1[(2 * i2 + 1) * 64 + l]);
        s_m1b[idx] = f2pack(mw1[(2 * i2) * 64 + 32 + l], mw1[(2 * i2 + 1) * 64 + 32 + l]);
    }
    for (int idx = tid; idx < 1024; idx += 256) {
        int i2 = idx >> 5, l = idx & 31;
        s_m2[idx] = f2pack(mw2[(2 * i2) * 32 + l], mw2[(2 * i2 + 1) * 32 + l]);
    }
    if (tid < 32) {
        s_bp[tid] = bp[tid]; s_mb2[tid] = mb2[tid]; s_g[tid] = n2g[tid]; s_b[tid] = n2b[tid];
        float A = stats[32 + tid] * in_g[tid];
        s_A[tid] = A;
        s_C[tid] = in_b[tid] - stats[tid] * A;
    }
    if (tid < 64) s_mb1[tid] = mb1[tid];
    __syncthreads();
    int lane = tid & 31, w = tid >> 5;
    int p0blk = blockIdx.x * 64;
    int pbase = p0blk + w * PPW;
    float* s_h = (float*)&s_ovl[w][0];

    float sc8[2][PPW];
#pragma unroll
    for (int it = 0; it < PPW; it++) {
        int p = pbase + it;
        sc8[0][it] = xhwc[p * 32 + lane];
        sc8[1][it] = t4[p * 32 + lane] * s_A[lane] + s_C[lane];
    }

    float osum[PPW];
#pragma unroll
    for (int it = 0; it < PPW; it++) osum[it] = 0.f;

#pragma unroll 1
    for (int z = 0; z < 2; z++) {
#pragma unroll
        for (int it = 0; it < PPW; it++)
            s_yn[w][it][lane] =
                __bfloat162float(attbase[(size_t)z * HWP * 32 + (pbase + it) * 32 + lane]);
        __syncwarp();
        float y[PPW];
        {
            u64 aq[PPW];
#pragma unroll
            for (int it = 0; it < PPW; it++) aq[it] = 0ULL;
#pragma unroll
            for (int i2 = 0; i2 < 16; i2++) {
                u64 wv = s_wp2[i2 * 32 + lane];
#pragma unroll
                for (int it = 0; it < PPW; it++) {
                    u64 x2 = *(const u64*)&s_yn[w][it][2 * i2];
                    aq[it] = f2fma(x2, wv, aq[it]);
                }
            }
#pragma unroll
            for (int it = 0; it < PPW; it++) {
                float2 fy = f2unpack(aq[it]);
                y[it] = fy.x + fy.y + s_bp[lane] + sc8[z][it];
            }
        }
        __syncwarp();
#pragma unroll 1
        for (int it = 0; it < PPW; it++) {
            float mean = warp_sum(y[it]) * (1.f / 32.f);
            float dv = y[it] - mean;
            float var = warp_sum(dv * dv) * (1.f / 32.f);
            s_yn[w][it][lane] = dv * rsqrtf(var + 1e-5f) * s_g[lane] + s_b[lane];
        }
        __syncwarp();
        {
            u64 ha[PPW];
#pragma unroll
            for (int it = 0; it < PPW; it++) ha[it] = 0ULL;
#pragma unroll
            for (int i2 = 0; i2 < 16; i2++) {
                u64 wv = s_m1a[i2 * 32 + lane];
#pragma unroll
                for (int it = 0; it < PPW; it++) {
                    u64 x2 = *(const u64*)&s_yn[w][it][2 * i2];
                    ha[it] = f2fma(x2, wv, ha[it]);
                }
            }
#pragma unroll
            for (int it = 0; it < PPW; it++) {
                float2 f0 = f2unpack(ha[it]);
                s_h[it * 64 + lane] = gelu_tanh(f0.x + f0.y + s_mb1[lane]);
            }
#pragma unroll
            for (int it = 0; it < PPW; it++) ha[it] = 0ULL;
#pragma unroll
            for (int i2 = 0; i2 < 16; i2++) {
                u64 wv = s_m1b[i2 * 32 + lane];
#pragma unroll
                for (int it = 0; it < PPW; it++) {
                    u64 x2 = *(const u64*)&s_yn[w][it][2 * i2];
                    ha[it] = f2fma(x2, wv, ha[it]);
                }
            }
#pragma unroll
            for (int it = 0; it < PPW; it++) {
                float2 f1 = f2unpack(ha[it]);
                s_h[it * 64 + 32 + lane] = gelu_tanh(f1.x + f1.y + s_mb1[lane + 32]);
            }
        }
        __syncwarp();
        {
            u64 r2[PPW];
#pragma unroll
            for (int it = 0; it < PPW; it++) r2[it] = 0ULL;
#pragma unroll
            for (int i2 = 0; i2 < 32; i2++) {
                u64 wv = s_m2[i2 * 32 + lane];
#pragma unroll
                for (int it = 0; it < PPW; it++) {
                    u64 g2 = *(const u64*)&s_h[it * 64 + 2 * i2];
                    r2[it] = f2fma(g2, wv, r2[it]);
                }
            }
#pragma unroll
            for (int it = 0; it < PPW; it++) {
                float2 fr = f2unpack(r2[it]);
                osum[it] += y[it] + fr.x + fr.y + s_mb2[lane];
            }
        }
        __syncwarp();
    }

    __syncthreads();
    float (*s_o)[33] = (float(*)[33])&s_ovl[0][0];
#pragma unroll
    for (int it = 0; it < PPW; it++) s_o[w * PPW + it][lane] = osum[it];
    __syncthreads();
#pragma unroll
    for (int e = tid; e < 2048; e += 256) {
        int c = e >> 6, px = e & 63;
        int gp = p0blk + px;
        out[c * HWP + gp] = s_o[px][c] + x_chw[c * HWP + gp];
    }
}

// ---------------- launch ----------------
extern "C" void kernel_launch(void* const* d_in, const int* in_sizes, int n_in,
                              void* d_out, int out_size) {
    const float* x    = (const float*)d_in[0];
    const float* dep  = (const float*)d_in[1];
    const int*   rpi  = (const int*)  d_in[2];
    const float* cw1  = (const float*)d_in[3];
    const float* cb1  = (const float*)d_in[4];
    const float* cw2  = (const float*)d_in[5];
    const float* cb2  = (const float*)d_in[6];
    const float* cw3  = (const float*)d_in[7];
    const float* cb3  = (const float*)d_in[8];
    const float* cw4  = (const float*)d_in[9];
    const float* cb4  = (const float*)d_in[10];
    const float* in_g = (const float*)d_in[11];
    const float* in_b = (const float*)d_in[12];
    const float* n1g  = (const float*)d_in[13];
    const float* n1b  = (const float*)d_in[14];
    const float* wq   = (const float*)d_in[15];
    const float* bq   = (const float*)d_in[16];
    const float* wkv  = (const float*)d_in[17];
    const float* bkv  = (const float*)d_in[18];
    const float* rpb  = (const float*)d_in[19];
    const float* wp   = (const float*)d_in[20];
    const float* bp   = (const float*)d_in[21];
    const float* n2g  = (const float*)d_in[22];
    const float* n2b  = (const float*)d_in[23];
    const float* mw1  = (const float*)d_in[24];
    const float* mb1  = (const float*)d_in[25];
    const float* mw2  = (const float*)d_in[26];
    const float* mb2  = (const float*)d_in[27];
    float* out = (float*)d_out;

    void *p_xhwc, *p_t4, *p_q, *p_kv, *p_att, *p_bias, *p_stats, *p_part;
    cudaGetSymbolAddress(&p_xhwc, g_xhwc);
    cudaGetSymbolAddress(&p_t4, g_t4);
    cudaGetSymbolAddress(&p_q, g_qbf);
    cudaGetSymbolAddress(&p_kv, g_kvbf);
    cudaGetSymbolAddress(&p_att, g_attbf);
    cudaGetSymbolAddress(&p_bias, g_biasF);
    cudaGetSymbolAddress(&p_stats, g_stats);
    cudaGetSymbolAddress(&p_part, g_part);

    cudaFuncSetAttribute(attn_kernel, cudaFuncAttributeMaxDynamicSharedMemorySize, SMEM_ATTN);

    chw2hwc_kernel<<<2048, dim3(32, 8)>>>(x, (float*)p_xhwc);
    stem_fused_kernel<<<256, 256>>>(dep, cw1, cb1, cw2, cb2, cw3, cb3, cw4, cb4,
                                    (float*)p_t4);
    inorm_part_kernel<<<512, 256>>>((float*)p_t4, (float*)p_part);
    inorm_final_kernel<<<1, 1024>>>((float*)p_part, (float*)p_stats);
    build_biasF_kernel<<<288, 256>>>(rpi, rpb, (u64*)p_bias);

    ln_qkv_kernel<<<HWP / (8 * PPW), 256>>>(
        (float*)p_xhwc, (float*)p_t4, (float*)p_stats, in_g, in_b, n1g, n1b,
        wq, bq, wkv, bkv, (__nv_bfloat16*)p_q, (__nv_bfloat16*)p_kv);
    attn_kernel<<<dim3(NWIN, 2), 256, SMEM_ATTN>>>((__nv_bfloat16*)p_q,
                                                   (__nv_bfloat16*)p_kv,
                                                   (u64*)p_bias,
                                                   (__nv_bfloat16*)p_att);
    proj_mlp_kernel<<<HWP / 64, 256>>>(
        (__nv_bfloat16*)p_att, (float*)p_xhwc, (float*)p_t4, x, (float*)p_stats,
        in_g, in_b, wp, bp, n2g, n2b, mw1, mb1, mw2, mb2, out);
}